// round 12
// baseline (speedup 1.0000x reference)
#include <cuda_runtime.h>
#include <cuda_fp16.h>
#include <cstdint>

#define NNODES 100000
#define EEDGES 1600000
#define HDIM   128

#define SCAN_BLK 1024
#define SCAN_T   256
#define NSCAN    ((NNODES + SCAN_BLK - 1) / SCAN_BLK)   // 98

#define MTILE   128
#define NTILES  ((NNODES + MTILE - 1) / MTILE)          // 782
#define PADH    136                                      // halves per padded row (272 B)
#define TILEB   (128 * PADH * 2)                         // 34816 B per fp16 tile
#define SMEM_L0 (4 * TILEB)                              // A_hi, A_lo, W_hi, W_lo
#define SMEM_F16 (3 * TILEB)                             // A, W_hi, W_lo

// ---------------------------------------------------------------------------
// Scratch (device globals)
// ---------------------------------------------------------------------------
__device__ __half g_h16a[(size_t)NNODES * HDIM];  // ping
__device__ __half g_h16b[(size_t)NNODES * HDIM];  // pong
__device__ float  g_dinv[NNODES];
__device__ int    g_deg[NNODES];
__device__ int    g_off[NNODES + 1];
__device__ int    g_cur[NNODES];
__device__ int    g_csr[EEDGES];
__device__ int    g_bsum[NSCAN];
__device__ int    g_bbase[NSCAN];
__device__ __half g_Wt[3][2][128 * 128];          // k-major W, fp16 hi/lo split

// ---------------------------------------------------------------------------
__device__ __forceinline__ uint32_t smem_u32(const void* p) {
    uint32_t a;
    asm("{ .reg .u64 t; cvta.to.shared.u64 t, %1; cvt.u32.u64 %0, t; }"
        : "=r"(a) : "l"(p));
    return a;
}

#define LDSM_X4(r, a) \
    asm volatile("ldmatrix.sync.aligned.m8n8.x4.shared.b16 {%0,%1,%2,%3}, [%4];" \
                 : "=r"((r)[0]), "=r"((r)[1]), "=r"((r)[2]), "=r"((r)[3]) : "r"(a))
#define LDSM_X4T(r, a) \
    asm volatile("ldmatrix.sync.aligned.m8n8.x4.trans.shared.b16 {%0,%1,%2,%3}, [%4];" \
                 : "=r"((r)[0]), "=r"((r)[1]), "=r"((r)[2]), "=r"((r)[3]) : "r"(a))
#define MMA_F16(c, a, b0, b1) \
    asm volatile("mma.sync.aligned.m16n8k16.row.col.f32.f16.f16.f32 " \
                 "{%0,%1,%2,%3}, {%4,%5,%6,%7}, {%8,%9}, {%0,%1,%2,%3};" \
                 : "+f"((c)[0]), "+f"((c)[1]), "+f"((c)[2]), "+f"((c)[3]) \
                 : "r"((a)[0]), "r"((a)[1]), "r"((a)[2]), "r"((a)[3]), \
                   "r"(b0), "r"(b1))

// ---------------------------------------------------------------------------
// Degree / CSR build
// ---------------------------------------------------------------------------
__global__ void deg_count(const int* __restrict__ dst) {
    int e = blockIdx.x * blockDim.x + threadIdx.x;
    if (e < EEDGES) atomicAdd(&g_deg[dst[e]], 1);
}
// scan1 also computes dinv = rsqrt(deg+1)
__global__ __launch_bounds__(SCAN_T)
void scan1() {
    __shared__ int sh[SCAN_T];
    int b = blockIdx.x, t = threadIdx.x;
    int base = b * SCAN_BLK + t * 4;
    int v[4];
#pragma unroll
    for (int j = 0; j < 4; j++) {
        int i = base + j;
        v[j] = (i < NNODES) ? g_deg[i] : 0;
        if (i < NNODES) g_dinv[i] = rsqrtf((float)v[j] + 1.0f);
    }
    int tot = v[0] + v[1] + v[2] + v[3];
    sh[t] = tot;
    __syncthreads();
    for (int o = 1; o < SCAN_T; o <<= 1) {
        int x = 0;
        if (t >= o) x = sh[t - o];
        __syncthreads();
        sh[t] += x;
        __syncthreads();
    }
    int run = sh[t] - tot;
#pragma unroll
    for (int j = 0; j < 4; j++) {
        int i = base + j;
        if (i < NNODES) g_off[i] = run;
        run += v[j];
    }
    if (t == SCAN_T - 1) g_bsum[b] = sh[t];
}
__global__ void scan2p() {
    __shared__ int sh[128];
    int t = threadIdx.x;
    int v = (t < NSCAN) ? g_bsum[t] : 0;
    sh[t] = v;
    __syncthreads();
    for (int o = 1; o < 128; o <<= 1) {
        int x = 0;
        if (t >= o) x = sh[t - o];
        __syncthreads();
        sh[t] += x;
        __syncthreads();
    }
    if (t < NSCAN) g_bbase[t] = sh[t] - v;
    if (t == 127) g_off[NNODES] = sh[127];
}
__global__ void scan3() {
    int i = blockIdx.x * blockDim.x + threadIdx.x;
    if (i < NNODES) {
        int v = g_off[i] + g_bbase[i / SCAN_BLK];
        g_off[i] = v;
        g_cur[i] = v;
    }
}
__global__ void csr_fill(const int* __restrict__ src, const int* __restrict__ dst) {
    int e = blockIdx.x * blockDim.x + threadIdx.x;
    if (e < EEDGES) {
        int d = dst[e];
        int slot = atomicAdd(&g_cur[d], 1);
        g_csr[slot] = src[e];
    }
}

// ---------------------------------------------------------------------------
// Prep: split W (k-major, [k][n]) into fp16 hi/lo (near-exact sum).
// ---------------------------------------------------------------------------
__global__ void prep_w(const float* __restrict__ W0, const float* __restrict__ W1,
                       const float* __restrict__ W2) {
    int idx = blockIdx.x * blockDim.x + threadIdx.x;
    if (idx >= 3 * 16384) return;
    int l = idx >> 14;
    int e = idx & 16383;
    const float* W = (l == 0) ? W0 : (l == 1) ? W1 : W2;
    float v = W[e];
    __half hi = __float2half_rn(v);
    __half lo = __float2half_rn(v - __half2float(hi));
    g_Wt[l][0][e] = hi;
    g_Wt[l][1][e] = lo;
}

// ---------------------------------------------------------------------------
// GEMM device helpers
// ---------------------------------------------------------------------------
__device__ __forceinline__ void fill_w_tiles(char* sm, uint32_t woff, int wl,
                                             int tid) {
    const uint4* whi = (const uint4*)g_Wt[wl][0];
    const uint4* wlo = (const uint4*)g_Wt[wl][1];
#pragma unroll
    for (int i = tid; i < 2048; i += 512) {
        int r  = i >> 4;
        int c4 = i & 15;
        uint32_t off = (uint32_t)r * (PADH * 2) + c4 * 16;
        *(uint4*)(sm + woff + off)         = __ldg(&whi[i]);
        *(uint4*)(sm + woff + TILEB + off) = __ldg(&wlo[i]);
    }
}

template <bool DUAL_A, bool SCALE>
__device__ __forceinline__ void mma_and_store(uint32_t uA, uint32_t uWhi,
                                              int wid, int lane, int bm,
                                              const float* dinv,
                                              __half* __restrict__ C16) {
    const uint32_t uWlo = uWhi + TILEB;
    const int mt = wid >> 1;
    const int nh = wid & 1;
    const int lr = lane & 15;
    const int lc = lane >> 4;

    float acc[8][4];
#pragma unroll
    for (int j = 0; j < 8; j++)
#pragma unroll
        for (int q = 0; q < 4; q++) acc[j][q] = 0.0f;

#pragma unroll
    for (int ks = 0; ks < 8; ks++) {
        uint32_t aoff = (uint32_t)(mt * 16 + lr) * (PADH * 2) + (ks * 16 + lc * 8) * 2;
        uint32_t aH[4], aL[4];
        LDSM_X4(aH, uA + aoff);
        if (DUAL_A) LDSM_X4(aL, uA + TILEB + aoff);

        uint32_t brow = (uint32_t)(ks * 16 + lr) * (PADH * 2);
#pragma unroll
        for (int p = 0; p < 4; p++) {
            uint32_t boff = brow + (nh * 64 + p * 16 + lc * 8) * 2;
            uint32_t bH[4], bL[4];
            LDSM_X4T(bH, uWhi + boff);
            LDSM_X4T(bL, uWlo + boff);
            MMA_F16(acc[2 * p],     aH, bH[0], bH[1]);
            MMA_F16(acc[2 * p + 1], aH, bH[2], bH[3]);
            MMA_F16(acc[2 * p],     aH, bL[0], bL[1]);
            MMA_F16(acc[2 * p + 1], aH, bL[2], bL[3]);
            if (DUAL_A) {
                MMA_F16(acc[2 * p],     aL, bH[0], bH[1]);
                MMA_F16(acc[2 * p + 1], aL, bH[2], bH[3]);
            }
        }
    }

    int row0 = bm + mt * 16 + (lane >> 2);
    int row1 = row0 + 8;
    float s0 = 1.f, s1 = 1.f;
    if (SCALE) {
        s0 = (row0 < NNODES) ? __ldg(&dinv[row0]) : 0.f;
        s1 = (row1 < NNODES) ? __ldg(&dinv[row1]) : 0.f;
    }
    int colb = nh * 64 + (lane & 3) * 2;
    if (row0 < NNODES) {
        __half* o = &C16[(size_t)row0 * 128 + colb];
#pragma unroll
        for (int j = 0; j < 8; j++)
            *(__half2*)(o + j * 8) = __floats2half2_rn(acc[j][0] * s0, acc[j][1] * s0);
    }
    if (row1 < NNODES) {
        __half* o = &C16[(size_t)row1 * 128 + colb];
#pragma unroll
        for (int j = 0; j < 8; j++)
            *(__half2*)(o + j * 8) = __floats2half2_rn(acc[j][2] * s1, acc[j][3] * s1);
    }
}

// ---------------------------------------------------------------------------
// Layer-0 GEMM (fp32 A, fp16 hi/lo split, NO dinv): h16 = fp16( x @ W0 )
// ---------------------------------------------------------------------------
__global__ __launch_bounds__(512, 1)
void gemm_f32(const float* __restrict__ A, __half* __restrict__ C16) {
    extern __shared__ char sm[];
    const int tid  = threadIdx.x;
    const int wid  = tid >> 5;
    const int lane = tid & 31;
    const int bm   = blockIdx.x * MTILE;
    const uint32_t uBase = smem_u32(sm);

    fill_w_tiles(sm, 2 * TILEB, 0, tid);

#pragma unroll
    for (int idx = tid; idx < MTILE * 32; idx += 512) {
        int r  = idx >> 5;
        int c4 = idx & 31;
        int row = bm + r;
        float4 v = make_float4(0.f, 0.f, 0.f, 0.f);
        if (row < NNODES)
            v = *(const float4*)&A[(size_t)row * 128 + c4 * 4];
        __half h0 = __float2half_rn(v.x), h1 = __float2half_rn(v.y);
        __half h2 = __float2half_rn(v.z), h3 = __float2half_rn(v.w);
        __half l0 = __float2half_rn(v.x - __half2float(h0));
        __half l1 = __float2half_rn(v.y - __half2float(h1));
        __half l2 = __float2half_rn(v.z - __half2float(h2));
        __half l3 = __float2half_rn(v.w - __half2float(h3));
        uint32_t off = (uint32_t)r * (PADH * 2) + c4 * 8;
        *(__half2*)(sm + off)             = __halves2half2(h0, h1);
        *(__half2*)(sm + off + 4)         = __halves2half2(h2, h3);
        *(__half2*)(sm + TILEB + off)     = __halves2half2(l0, l1);
        *(__half2*)(sm + TILEB + off + 4) = __halves2half2(l2, l3);
    }
    __syncthreads();

    mma_and_store<true, false>(uBase, uBase + 2 * TILEB, wid, lane, bm, nullptr, C16);
}

// ---------------------------------------------------------------------------
// Layers 1..2 GEMM (fp16 A, exact): out = fp16( dinv*(A@W) )
// ---------------------------------------------------------------------------
__global__ __launch_bounds__(512, 2)
void gemm_f16(const __half* __restrict__ A16, int wl,
              const float* __restrict__ dinv, __half* __restrict__ C16) {
    extern __shared__ char sm[];
    const int tid  = threadIdx.x;
    const int wid  = tid >> 5;
    const int lane = tid & 31;
    const int bm   = blockIdx.x * MTILE;
    const uint32_t uBase = smem_u32(sm);

    fill_w_tiles(sm, TILEB, wl, tid);

    const uint2* ap = (const uint2*)A16;
#pragma unroll
    for (int idx = tid; idx < MTILE * 32; idx += 512) {
        int r  = idx >> 5;
        int c4 = idx & 31;
        int row = bm + r;
        uint2 u = make_uint2(0u, 0u);
        if (row < NNODES) u = __ldg(&ap[(size_t)row * 32 + c4]);
        uint32_t off = (uint32_t)r * (PADH * 2) + c4 * 8;
        *(uint2*)(sm + off) = u;
    }
    __syncthreads();

    mma_and_store<false, true>(uBase, uBase + TILEB, wid, lane, bm, dinv, C16);
}

// ---------------------------------------------------------------------------
// Gather: one warp per node. Masked 8-deep batch loop — NO scalar tail, so
// every edge's idx->row load chain issues at MLP=8. Out-of-range slots clamp
// to the last edge (L1-duplicate) and get weight 0.
// SRC_SCALED: h already carries dinv[src]. FINAL_F32: write fp32.
// ---------------------------------------------------------------------------
#define ACCW(u, wgt) { \
    float2 _a = __half22float2(*(const __half2*)&(u).x); \
    float2 _b = __half22float2(*(const __half2*)&(u).y); \
    acc.x += _a.x * (wgt); acc.y += _a.y * (wgt); \
    acc.z += _b.x * (wgt); acc.w += _b.y * (wgt); }

template <bool SRC_SCALED, bool FINAL_F32>
__global__ __launch_bounds__(256)
void gather_k(const __half* __restrict__ hs, const float* __restrict__ bias,
              void* __restrict__ outv) {
    int w = (int)((blockIdx.x * (unsigned)blockDim.x + threadIdx.x) >> 5);
    if (w >= NNODES) return;
    int lane = threadIdx.x & 31;
    const uint2* hp = (const uint2*)hs;

    int e    = g_off[w];
    int eend = g_off[w + 1];
    int elast = eend - 1;
    float sc = __ldg(&g_dinv[w]);

    float4 acc = make_float4(0.f, 0.f, 0.f, 0.f);
    {
        uint2 u = __ldg(&hp[w * 32 + lane]);
        float wgt = SRC_SCALED ? 1.f : sc;
        ACCW(u, wgt)
    }

    for (; e < eend; e += 8) {
        int e0 = e,               e1 = min(e + 1, elast);
        int e2 = min(e + 2, elast), e3 = min(e + 3, elast);
        int e4 = min(e + 4, elast), e5 = min(e + 5, elast);
        int e6 = min(e + 6, elast), e7 = min(e + 7, elast);
        int s0 = __ldg(&g_csr[e0]);
        int s1 = __ldg(&g_csr[e1]);
        int s2 = __ldg(&g_csr[e2]);
        int s3 = __ldg(&g_csr[e3]);
        int s4 = __ldg(&g_csr[e4]);
        int s5 = __ldg(&g_csr[e5]);
        int s6 = __ldg(&g_csr[e6]);
        int s7 = __ldg(&g_csr[e7]);
        uint2 u0 = __ldg(&hp[s0 * 32 + lane]);
        uint2 u1 = __ldg(&hp[s1 * 32 + lane]);
        uint2 u2 = __ldg(&hp[s2 * 32 + lane]);
        uint2 u3 = __ldg(&hp[s3 * 32 + lane]);
        uint2 u4 = __ldg(&hp[s4 * 32 + lane]);
        uint2 u5 = __ldg(&hp[s5 * 32 + lane]);
        uint2 u6 = __ldg(&hp[s6 * 32 + lane]);
        uint2 u7 = __ldg(&hp[s7 * 32 + lane]);
        float w0, w1, w2, w3, w4, w5, w6, w7;
        if (SRC_SCALED) {
            w0 = 1.f;
            w1 = (e + 1 < eend) ? 1.f : 0.f;
            w2 = (e + 2 < eend) ? 1.f : 0.f;
            w3 = (e + 3 < eend) ? 1.f : 0.f;
            w4 = (e + 4 < eend) ? 1.f : 0.f;
            w5 = (e + 5 < eend) ? 1.f : 0.f;
            w6 = (e + 6 < eend) ? 1.f : 0.f;
            w7 = (e + 7 < eend) ? 1.f : 0.f;
        } else {
            w0 = __ldg(&g_dinv[s0]);
            w1 = (e + 1 < eend) ? __ldg(&g_dinv[s1]) : 0.f;
            w2 = (e + 2 < eend) ? __ldg(&g_dinv[s2]) : 0.f;
            w3 = (e + 3 < eend) ? __ldg(&g_dinv[s3]) : 0.f;
            w4 = (e + 4 < eend) ? __ldg(&g_dinv[s4]) : 0.f;
            w5 = (e + 5 < eend) ? __ldg(&g_dinv[s5]) : 0.f;
            w6 = (e + 6 < eend) ? __ldg(&g_dinv[s6]) : 0.f;
            w7 = (e + 7 < eend) ? __ldg(&g_dinv[s7]) : 0.f;
        }
        ACCW(u0, w0) ACCW(u1, w1) ACCW(u2, w2) ACCW(u3, w3)
        ACCW(u4, w4) ACCW(u5, w5) ACCW(u6, w6) ACCW(u7, w7)
    }

    float4 bb = *(const float4*)&bias[lane * 4];
    acc.x = fmaxf(acc.x * sc + bb.x, 0.f);
    acc.y = fmaxf(acc.y * sc + bb.y, 0.f);
    acc.z = fmaxf(acc.z * sc + bb.z, 0.f);
    acc.w = fmaxf(acc.w * sc + bb.w, 0.f);

    if (FINAL_F32) {
        ((float4*)outv)[w * 32 + lane] = acc;
    } else {
        __half2 o0 = __floats2half2_rn(acc.x, acc.y);
        __half2 o1 = __floats2half2_rn(acc.z, acc.w);
        uint2 ou;
        ou.x = *(const uint32_t*)&o0;
        ou.y = *(const uint32_t*)&o1;
        ((uint2*)outv)[w * 32 + lane] = ou;
    }
}
#undef ACCW

// ---------------------------------------------------------------------------
extern "C" void kernel_launch(void* const* d_in, const int* in_sizes, int n_in,
                              void* d_out, int out_size) {
    const float* x  = (const float*)d_in[0];
    const int*   ei = (const int*)d_in[1];
    const float* W0 = (const float*)d_in[2];
    const float* b0 = (const float*)d_in[3];
    const float* W1 = (const float*)d_in[4];
    const float* b1 = (const float*)d_in[5];
    const float* W2 = (const float*)d_in[6];
    const float* b2 = (const float*)d_in[7];
    const int* src = ei;
    const int* dst = ei + EEDGES;

    __half *ha, *hb;
    float* dinv;
    int*   deg;
    cudaGetSymbolAddress((void**)&ha, g_h16a);
    cudaGetSymbolAddress((void**)&hb, g_h16b);
    cudaGetSymbolAddress((void**)&dinv, g_dinv);
    cudaGetSymbolAddress((void**)&deg,  g_deg);

    cudaFuncSetAttribute(gemm_f32, cudaFuncAttributeMaxDynamicSharedMemorySize, SMEM_L0);
    cudaFuncSetAttribute(gemm_f16, cudaFuncAttributeMaxDynamicSharedMemorySize, SMEM_F16);

    static cudaStream_t s2 = nullptr;
    static cudaEvent_t evFork = nullptr, evJoin = nullptr;
    if (!s2) {
        cudaStreamCreateWithFlags(&s2, cudaStreamNonBlocking);
        cudaEventCreateWithFlags(&evFork, cudaEventDisableTiming);
        cudaEventCreateWithFlags(&evJoin, cudaEventDisableTiming);
    }

    // Fork: side stream does W prep + layer-0 GEMM (independent of CSR chain)
    cudaEventRecord(evFork, 0);
    cudaStreamWaitEvent(s2, evFork, 0);
    prep_w<<<(3 * 16384 + 255) / 256, 256, 0, s2>>>(W0, W1, W2);
    gemm_f32<<<NTILES, 512, SMEM_L0, s2>>>(x, ha);
    cudaEventRecord(evJoin, s2);

    // Main stream: degree + CSR build
    cudaMemsetAsync(deg, 0, NNODES * sizeof(int), 0);
    deg_count<<<(EEDGES + 255) / 256, 256>>>(dst);
    scan1<<<NSCAN, SCAN_T>>>();
    scan2p<<<1, 128>>>();
    scan3<<<(NNODES + 255) / 256, 256>>>();
    csr_fill<<<(EEDGES + 255) / 256, 256>>>(src, dst);

    // Join, then the serial layer chain
    cudaStreamWaitEvent(0, evJoin, 0);

    const int gather_blocks = (NNODES + 7) / 8;
    gather_k<false, false><<<gather_blocks, 256>>>(ha, b0, hb);
    gemm_f16<<<NTILES, 512, SMEM_F16>>>(hb, 1, dinv, ha);
    gather_k<true, false><<<gather_blocks, 256>>>(ha, b1, hb);
    gemm_f16<<<NTILES, 512, SMEM_F16>>>(hb, 2, dinv, ha);
    gather_k<true, true><<<gather_blocks, 256>>>(ha, b2, d_out);
}

// round 13
// speedup vs baseline: 1.1039x; 1.1039x over previous
#include <cuda_runtime.h>
#include <cuda_fp16.h>
#include <cstdint>

#define NNODES 100000
#define EEDGES 1600000
#define HDIM   128

#define SCAN_BLK 1024
#define SCAN_T   256
#define NSCAN    ((NNODES + SCAN_BLK - 1) / SCAN_BLK)   // 98

#define MTILE   128
#define NTILES  ((NNODES + MTILE - 1) / MTILE)          // 782
#define PADH    136                                      // halves per padded row (272 B)
#define TILEB   (128 * PADH * 2)                         // 34816 B per fp16 tile
#define SMEM_L0 (4 * TILEB)                              // A_hi, A_lo, W_hi, W_lo
#define SMEM_F16 (3 * TILEB)                             // A, W_hi, W_lo

// ---------------------------------------------------------------------------
// Scratch (device globals)
// ---------------------------------------------------------------------------
__device__ __half g_h16a[(size_t)NNODES * HDIM];  // ping
__device__ __half g_h16b[(size_t)NNODES * HDIM];  // pong
__device__ float  g_dinv[NNODES];
__device__ int    g_deg[NNODES];
__device__ int    g_off[NNODES + 1];
__device__ int    g_cur[NNODES];
__device__ int    g_csr[EEDGES];
__device__ int    g_bsum[NSCAN];
__device__ int    g_bbase[NSCAN];
__device__ __half g_Wt[3][2][128 * 128];          // k-major W, fp16 hi/lo split

// ---------------------------------------------------------------------------
__device__ __forceinline__ uint32_t smem_u32(const void* p) {
    uint32_t a;
    asm("{ .reg .u64 t; cvta.to.shared.u64 t, %1; cvt.u32.u64 %0, t; }"
        : "=r"(a) : "l"(p));
    return a;
}

#define LDSM_X4(r, a) \
    asm volatile("ldmatrix.sync.aligned.m8n8.x4.shared.b16 {%0,%1,%2,%3}, [%4];" \
                 : "=r"((r)[0]), "=r"((r)[1]), "=r"((r)[2]), "=r"((r)[3]) : "r"(a))
#define LDSM_X4T(r, a) \
    asm volatile("ldmatrix.sync.aligned.m8n8.x4.trans.shared.b16 {%0,%1,%2,%3}, [%4];" \
                 : "=r"((r)[0]), "=r"((r)[1]), "=r"((r)[2]), "=r"((r)[3]) : "r"(a))
#define MMA_F16(c, a, b0, b1) \
    asm volatile("mma.sync.aligned.m16n8k16.row.col.f32.f16.f16.f32 " \
                 "{%0,%1,%2,%3}, {%4,%5,%6,%7}, {%8,%9}, {%0,%1,%2,%3};" \
                 : "+f"((c)[0]), "+f"((c)[1]), "+f"((c)[2]), "+f"((c)[3]) \
                 : "r"((a)[0]), "r"((a)[1]), "r"((a)[2]), "r"((a)[3]), \
                   "r"(b0), "r"(b1))

// ---------------------------------------------------------------------------
// Degree / CSR build
// ---------------------------------------------------------------------------
__global__ void deg_count(const int* __restrict__ dst) {
    int e = blockIdx.x * blockDim.x + threadIdx.x;
    if (e < EEDGES) atomicAdd(&g_deg[dst[e]], 1);
}
// scan1 also computes dinv = rsqrt(deg+1)
__global__ __launch_bounds__(SCAN_T)
void scan1() {
    __shared__ int sh[SCAN_T];
    int b = blockIdx.x, t = threadIdx.x;
    int base = b * SCAN_BLK + t * 4;
    int v[4];
#pragma unroll
    for (int j = 0; j < 4; j++) {
        int i = base + j;
        v[j] = (i < NNODES) ? g_deg[i] : 0;
        if (i < NNODES) g_dinv[i] = rsqrtf((float)v[j] + 1.0f);
    }
    int tot = v[0] + v[1] + v[2] + v[3];
    sh[t] = tot;
    __syncthreads();
    for (int o = 1; o < SCAN_T; o <<= 1) {
        int x = 0;
        if (t >= o) x = sh[t - o];
        __syncthreads();
        sh[t] += x;
        __syncthreads();
    }
    int run = sh[t] - tot;
#pragma unroll
    for (int j = 0; j < 4; j++) {
        int i = base + j;
        if (i < NNODES) g_off[i] = run;
        run += v[j];
    }
    if (t == SCAN_T - 1) g_bsum[b] = sh[t];
}
__global__ void scan2p() {
    __shared__ int sh[128];
    int t = threadIdx.x;
    int v = (t < NSCAN) ? g_bsum[t] : 0;
    sh[t] = v;
    __syncthreads();
    for (int o = 1; o < 128; o <<= 1) {
        int x = 0;
        if (t >= o) x = sh[t - o];
        __syncthreads();
        sh[t] += x;
        __syncthreads();
    }
    if (t < NSCAN) g_bbase[t] = sh[t] - v;
    if (t == 127) g_off[NNODES] = sh[127];
}
__global__ void scan3() {
    int i = blockIdx.x * blockDim.x + threadIdx.x;
    if (i < NNODES) {
        int v = g_off[i] + g_bbase[i / SCAN_BLK];
        g_off[i] = v;
        g_cur[i] = v;
    }
}
__global__ void csr_fill(const int* __restrict__ src, const int* __restrict__ dst) {
    int e = blockIdx.x * blockDim.x + threadIdx.x;
    if (e < EEDGES) {
        int d = dst[e];
        int slot = atomicAdd(&g_cur[d], 1);
        g_csr[slot] = src[e];
    }
}

// ---------------------------------------------------------------------------
// Prep: split W (k-major, [k][n]) into fp16 hi/lo (near-exact sum).
// ---------------------------------------------------------------------------
__global__ void prep_w(const float* __restrict__ W0, const float* __restrict__ W1,
                       const float* __restrict__ W2) {
    int idx = blockIdx.x * blockDim.x + threadIdx.x;
    if (idx >= 3 * 16384) return;
    int l = idx >> 14;
    int e = idx & 16383;
    const float* W = (l == 0) ? W0 : (l == 1) ? W1 : W2;
    float v = W[e];
    __half hi = __float2half_rn(v);
    __half lo = __float2half_rn(v - __half2float(hi));
    g_Wt[l][0][e] = hi;
    g_Wt[l][1][e] = lo;
}

// ---------------------------------------------------------------------------
// GEMM device helpers
// ---------------------------------------------------------------------------
__device__ __forceinline__ void fill_w_tiles(char* sm, uint32_t woff, int wl,
                                             int tid) {
    const uint4* whi = (const uint4*)g_Wt[wl][0];
    const uint4* wlo = (const uint4*)g_Wt[wl][1];
#pragma unroll
    for (int i = tid; i < 2048; i += 512) {
        int r  = i >> 4;
        int c4 = i & 15;
        uint32_t off = (uint32_t)r * (PADH * 2) + c4 * 16;
        *(uint4*)(sm + woff + off)         = __ldg(&whi[i]);
        *(uint4*)(sm + woff + TILEB + off) = __ldg(&wlo[i]);
    }
}

template <bool DUAL_A, bool SCALE>
__device__ __forceinline__ void mma_and_store(uint32_t uA, uint32_t uWhi,
                                              int wid, int lane, int bm,
                                              const float* dinv,
                                              __half* __restrict__ C16) {
    const uint32_t uWlo = uWhi + TILEB;
    const int mt = wid >> 1;
    const int nh = wid & 1;
    const int lr = lane & 15;
    const int lc = lane >> 4;

    float acc[8][4];
#pragma unroll
    for (int j = 0; j < 8; j++)
#pragma unroll
        for (int q = 0; q < 4; q++) acc[j][q] = 0.0f;

#pragma unroll
    for (int ks = 0; ks < 8; ks++) {
        uint32_t aoff = (uint32_t)(mt * 16 + lr) * (PADH * 2) + (ks * 16 + lc * 8) * 2;
        uint32_t aH[4], aL[4];
        LDSM_X4(aH, uA + aoff);
        if (DUAL_A) LDSM_X4(aL, uA + TILEB + aoff);

        uint32_t brow = (uint32_t)(ks * 16 + lr) * (PADH * 2);
#pragma unroll
        for (int p = 0; p < 4; p++) {
            uint32_t boff = brow + (nh * 64 + p * 16 + lc * 8) * 2;
            uint32_t bH[4], bL[4];
            LDSM_X4T(bH, uWhi + boff);
            LDSM_X4T(bL, uWlo + boff);
            MMA_F16(acc[2 * p],     aH, bH[0], bH[1]);
            MMA_F16(acc[2 * p + 1], aH, bH[2], bH[3]);
            MMA_F16(acc[2 * p],     aH, bL[0], bL[1]);
            MMA_F16(acc[2 * p + 1], aH, bL[2], bL[3]);
            if (DUAL_A) {
                MMA_F16(acc[2 * p],     aL, bH[0], bH[1]);
                MMA_F16(acc[2 * p + 1], aL, bH[2], bH[3]);
            }
        }
    }

    int row0 = bm + mt * 16 + (lane >> 2);
    int row1 = row0 + 8;
    float s0 = 1.f, s1 = 1.f;
    if (SCALE) {
        s0 = (row0 < NNODES) ? __ldg(&dinv[row0]) : 0.f;
        s1 = (row1 < NNODES) ? __ldg(&dinv[row1]) : 0.f;
    }
    int colb = nh * 64 + (lane & 3) * 2;
    if (row0 < NNODES) {
        __half* o = &C16[(size_t)row0 * 128 + colb];
#pragma unroll
        for (int j = 0; j < 8; j++)
            *(__half2*)(o + j * 8) = __floats2half2_rn(acc[j][0] * s0, acc[j][1] * s0);
    }
    if (row1 < NNODES) {
        __half* o = &C16[(size_t)row1 * 128 + colb];
#pragma unroll
        for (int j = 0; j < 8; j++)
            *(__half2*)(o + j * 8) = __floats2half2_rn(acc[j][2] * s1, acc[j][3] * s1);
    }
}

// ---------------------------------------------------------------------------
// Layer-0 GEMM (fp32 A, fp16 hi/lo split, NO dinv): h16 = fp16( x @ W0 )
// ---------------------------------------------------------------------------
__global__ __launch_bounds__(512, 1)
void gemm_f32(const float* __restrict__ A, __half* __restrict__ C16) {
    extern __shared__ char sm[];
    const int tid  = threadIdx.x;
    const int wid  = tid >> 5;
    const int lane = tid & 31;
    const int bm   = blockIdx.x * MTILE;
    const uint32_t uBase = smem_u32(sm);

    fill_w_tiles(sm, 2 * TILEB, 0, tid);

#pragma unroll
    for (int idx = tid; idx < MTILE * 32; idx += 512) {
        int r  = idx >> 5;
        int c4 = idx & 31;
        int row = bm + r;
        float4 v = make_float4(0.f, 0.f, 0.f, 0.f);
        if (row < NNODES)
            v = *(const float4*)&A[(size_t)row * 128 + c4 * 4];
        __half h0 = __float2half_rn(v.x), h1 = __float2half_rn(v.y);
        __half h2 = __float2half_rn(v.z), h3 = __float2half_rn(v.w);
        __half l0 = __float2half_rn(v.x - __half2float(h0));
        __half l1 = __float2half_rn(v.y - __half2float(h1));
        __half l2 = __float2half_rn(v.z - __half2float(h2));
        __half l3 = __float2half_rn(v.w - __half2float(h3));
        uint32_t off = (uint32_t)r * (PADH * 2) + c4 * 8;
        *(__half2*)(sm + off)             = __halves2half2(h0, h1);
        *(__half2*)(sm + off + 4)         = __halves2half2(h2, h3);
        *(__half2*)(sm + TILEB + off)     = __halves2half2(l0, l1);
        *(__half2*)(sm + TILEB + off + 4) = __halves2half2(l2, l3);
    }
    __syncthreads();

    mma_and_store<true, false>(uBase, uBase + 2 * TILEB, wid, lane, bm, nullptr, C16);
}

// ---------------------------------------------------------------------------
// Layers 1..2 GEMM (fp16 A, exact): out = fp16( dinv*(A@W) )
// ---------------------------------------------------------------------------
__global__ __launch_bounds__(512, 2)
void gemm_f16(const __half* __restrict__ A16, int wl,
              const float* __restrict__ dinv, __half* __restrict__ C16) {
    extern __shared__ char sm[];
    const int tid  = threadIdx.x;
    const int wid  = tid >> 5;
    const int lane = tid & 31;
    const int bm   = blockIdx.x * MTILE;
    const uint32_t uBase = smem_u32(sm);

    fill_w_tiles(sm, TILEB, wl, tid);

    const uint2* ap = (const uint2*)A16;
#pragma unroll
    for (int idx = tid; idx < MTILE * 32; idx += 512) {
        int r  = idx >> 5;
        int c4 = idx & 31;
        int row = bm + r;
        uint2 u = make_uint2(0u, 0u);
        if (row < NNODES) u = __ldg(&ap[(size_t)row * 32 + c4]);
        uint32_t off = (uint32_t)r * (PADH * 2) + c4 * 8;
        *(uint2*)(sm + off) = u;
    }
    __syncthreads();

    mma_and_store<false, true>(uBase, uBase + TILEB, wid, lane, bm, dinv, C16);
}

// ---------------------------------------------------------------------------
// Gather: one warp per node. 8-deep full batches + ONE predicated masked
// batch for the remainder (predicated-off loads issue no transaction, so no
// extra traffic — unlike clamped duplicates). fp32 accumulate.
// SRC_SCALED: h already carries dinv[src]. FINAL_F32: write fp32.
// ---------------------------------------------------------------------------
#define ACCW(u, wgt) { \
    float2 _a = __half22float2(*(const __half2*)&(u).x); \
    float2 _b = __half22float2(*(const __half2*)&(u).y); \
    acc.x += _a.x * (wgt); acc.y += _a.y * (wgt); \
    acc.z += _b.x * (wgt); acc.w += _b.y * (wgt); }

template <bool SRC_SCALED, bool FINAL_F32>
__global__ __launch_bounds__(256)
void gather_k(const __half* __restrict__ hs, const float* __restrict__ bias,
              void* __restrict__ outv) {
    int w = (int)((blockIdx.x * (unsigned)blockDim.x + threadIdx.x) >> 5);
    if (w >= NNODES) return;
    int lane = threadIdx.x & 31;
    const uint2* hp = (const uint2*)hs;

    int e    = g_off[w];
    int eend = g_off[w + 1];
    float sc = __ldg(&g_dinv[w]);

    float4 acc = make_float4(0.f, 0.f, 0.f, 0.f);
    {
        uint2 u = __ldg(&hp[w * 32 + lane]);
        float wgt = SRC_SCALED ? 1.f : sc;
        ACCW(u, wgt)
    }

    // Full 8-batches
    for (; e + 8 <= eend; e += 8) {
        int s0 = __ldg(&g_csr[e + 0]);
        int s1 = __ldg(&g_csr[e + 1]);
        int s2 = __ldg(&g_csr[e + 2]);
        int s3 = __ldg(&g_csr[e + 3]);
        int s4 = __ldg(&g_csr[e + 4]);
        int s5 = __ldg(&g_csr[e + 5]);
        int s6 = __ldg(&g_csr[e + 6]);
        int s7 = __ldg(&g_csr[e + 7]);
        uint2 u0 = __ldg(&hp[s0 * 32 + lane]);
        uint2 u1 = __ldg(&hp[s1 * 32 + lane]);
        uint2 u2 = __ldg(&hp[s2 * 32 + lane]);
        uint2 u3 = __ldg(&hp[s3 * 32 + lane]);
        uint2 u4 = __ldg(&hp[s4 * 32 + lane]);
        uint2 u5 = __ldg(&hp[s5 * 32 + lane]);
        uint2 u6 = __ldg(&hp[s6 * 32 + lane]);
        uint2 u7 = __ldg(&hp[s7 * 32 + lane]);
        if (SRC_SCALED) {
            ACCW(u0, 1.f) ACCW(u1, 1.f) ACCW(u2, 1.f) ACCW(u3, 1.f)
            ACCW(u4, 1.f) ACCW(u5, 1.f) ACCW(u6, 1.f) ACCW(u7, 1.f)
        } else {
            ACCW(u0, __ldg(&g_dinv[s0])) ACCW(u1, __ldg(&g_dinv[s1]))
            ACCW(u2, __ldg(&g_dinv[s2])) ACCW(u3, __ldg(&g_dinv[s3]))
            ACCW(u4, __ldg(&g_dinv[s4])) ACCW(u5, __ldg(&g_dinv[s5]))
            ACCW(u6, __ldg(&g_dinv[s6])) ACCW(u7, __ldg(&g_dinv[s7]))
        }
    }

    // Remainder: one masked batch; predicated loads, zero-fill when out-of-range.
    if (e < eend) {
        const uint2 z = make_uint2(0u, 0u);
        int s0 = __ldg(&g_csr[e]);
        int s1 = (e + 1 < eend) ? __ldg(&g_csr[e + 1]) : 0;
        int s2 = (e + 2 < eend) ? __ldg(&g_csr[e + 2]) : 0;
        int s3 = (e + 3 < eend) ? __ldg(&g_csr[e + 3]) : 0;
        int s4 = (e + 4 < eend) ? __ldg(&g_csr[e + 4]) : 0;
        int s5 = (e + 5 < eend) ? __ldg(&g_csr[e + 5]) : 0;
        int s6 = (e + 6 < eend) ? __ldg(&g_csr[e + 6]) : 0;
        uint2 u0 = __ldg(&hp[s0 * 32 + lane]);
        uint2 u1 = (e + 1 < eend) ? __ldg(&hp[s1 * 32 + lane]) : z;
        uint2 u2 = (e + 2 < eend) ? __ldg(&hp[s2 * 32 + lane]) : z;
        uint2 u3 = (e + 3 < eend) ? __ldg(&hp[s3 * 32 + lane]) : z;
        uint2 u4 = (e + 4 < eend) ? __ldg(&hp[s4 * 32 + lane]) : z;
        uint2 u5 = (e + 5 < eend) ? __ldg(&hp[s5 * 32 + lane]) : z;
        uint2 u6 = (e + 6 < eend) ? __ldg(&hp[s6 * 32 + lane]) : z;
        if (SRC_SCALED) {
            ACCW(u0, 1.f) ACCW(u1, 1.f) ACCW(u2, 1.f) ACCW(u3, 1.f)
            ACCW(u4, 1.f) ACCW(u5, 1.f) ACCW(u6, 1.f)
        } else {
            float w0 = __ldg(&g_dinv[s0]);
            float w1 = (e + 1 < eend) ? __ldg(&g_dinv[s1]) : 0.f;
            float w2 = (e + 2 < eend) ? __ldg(&g_dinv[s2]) : 0.f;
            float w3 = (e + 3 < eend) ? __ldg(&g_dinv[s3]) : 0.f;
            float w4 = (e + 4 < eend) ? __ldg(&g_dinv[s4]) : 0.f;
            float w5 = (e + 5 < eend) ? __ldg(&g_dinv[s5]) : 0.f;
            float w6 = (e + 6 < eend) ? __ldg(&g_dinv[s6]) : 0.f;
            ACCW(u0, w0) ACCW(u1, w1) ACCW(u2, w2) ACCW(u3, w3)
            ACCW(u4, w4) ACCW(u5, w5) ACCW(u6, w6)
        }
    }

    float4 bb = *(const float4*)&bias[lane * 4];
    acc.x = fmaxf(acc.x * sc + bb.x, 0.f);
    acc.y = fmaxf(acc.y * sc + bb.y, 0.f);
    acc.z = fmaxf(acc.z * sc + bb.z, 0.f);
    acc.w = fmaxf(acc.w * sc + bb.w, 0.f);

    if (FINAL_F32) {
        ((float4*)outv)[w * 32 + lane] = acc;
    } else {
        __half2 o0 = __floats2half2_rn(acc.x, acc.y);
        __half2 o1 = __floats2half2_rn(acc.z, acc.w);
        uint2 ou;
        ou.x = *(const uint32_t*)&o0;
        ou.y = *(const uint32_t*)&o1;
        ((uint2*)outv)[w * 32 + lane] = ou;
    }
}
#undef ACCW

// ---------------------------------------------------------------------------
extern "C" void kernel_launch(void* const* d_in, const int* in_sizes, int n_in,
                              void* d_out, int out_size) {
    const float* x  = (const float*)d_in[0];
    const int*   ei = (const int*)d_in[1];
    const float* W0 = (const float*)d_in[2];
    const float* b0 = (const float*)d_in[3];
    const float* W1 = (const float*)d_in[4];
    const float* b1 = (const float*)d_in[5];
    const float* W2 = (const float*)d_in[6];
    const float* b2 = (const float*)d_in[7];
    const int* src = ei;
    const int* dst = ei + EEDGES;

    __half *ha, *hb;
    float* dinv;
    int*   deg;
    cudaGetSymbolAddress((void**)&ha, g_h16a);
    cudaGetSymbolAddress((void**)&hb, g_h16b);
    cudaGetSymbolAddress((void**)&dinv, g_dinv);
    cudaGetSymbolAddress((void**)&deg,  g_deg);

    cudaFuncSetAttribute(gemm_f32, cudaFuncAttributeMaxDynamicSharedMemorySize, SMEM_L0);
    cudaFuncSetAttribute(gemm_f16, cudaFuncAttributeMaxDynamicSharedMemorySize, SMEM_F16);

    static cudaStream_t s2 = nullptr;
    static cudaEvent_t evFork = nullptr, evJoin = nullptr;
    if (!s2) {
        cudaStreamCreateWithFlags(&s2, cudaStreamNonBlocking);
        cudaEventCreateWithFlags(&evFork, cudaEventDisableTiming);
        cudaEventCreateWithFlags(&evJoin, cudaEventDisableTiming);
    }

    // Fork: side stream does W prep + layer-0 GEMM (independent of CSR chain)
    cudaEventRecord(evFork, 0);
    cudaStreamWaitEvent(s2, evFork, 0);
    prep_w<<<(3 * 16384 + 255) / 256, 256, 0, s2>>>(W0, W1, W2);
    gemm_f32<<<NTILES, 512, SMEM_L0, s2>>>(x, ha);
    cudaEventRecord(evJoin, s2);

    // Main stream: degree + CSR build
    cudaMemsetAsync(deg, 0, NNODES * sizeof(int), 0);
    deg_count<<<(EEDGES + 255) / 256, 256>>>(dst);
    scan1<<<NSCAN, SCAN_T>>>();
    scan2p<<<1, 128>>>();
    scan3<<<(NNODES + 255) / 256, 256>>>();
    csr_fill<<<(EEDGES + 255) / 256, 256>>>(src, dst);

    // Join, then the serial layer chain
    cudaStreamWaitEvent(0, evJoin, 0);

    const int gather_blocks = (NNODES + 7) / 8;
    gather_k<false, false><<<gather_blocks, 256>>>(ha, b0, hb);
    gemm_f16<<<NTILES, 512, SMEM_F16>>>(hb, 1, dinv, ha);
    gather_k<true, false><<<gather_blocks, 256>>>(ha, b1, hb);
    gemm_f16<<<NTILES, 512, SMEM_F16>>>(hb, 2, dinv, ha);
    gather_k<true, true><<<gather_blocks, 256>>>(ha, b2, d_out);
}

// round 14
// speedup vs baseline: 1.1489x; 1.0408x over previous
#include <cuda_runtime.h>
#include <cuda_fp16.h>
#include <cstdint>

#define NNODES 100000
#define EEDGES 1600000
#define HDIM   128

#define SCAN_BLK 1024
#define SCAN_T   256
#define NSCAN    ((NNODES + SCAN_BLK - 1) / SCAN_BLK)   // 98

#define MTILE   128
#define NTILES  ((NNODES + MTILE - 1) / MTILE)          // 782
#define PADH    136                                      // halves per padded row (272 B)
#define TILEB   (128 * PADH * 2)                         // 34816 B per fp16 tile
#define SMEM_L0 (4 * TILEB)                              // A_hi, A_lo, W_hi, W_lo
#define SMEM_F16 (3 * TILEB)                             // A, W_hi, W_lo

#define GBLK 64                                          // gather block threads

// ---------------------------------------------------------------------------
// Scratch (device globals)
// ---------------------------------------------------------------------------
__device__ __half g_h16a[(size_t)NNODES * HDIM];  // ping
__device__ __half g_h16b[(size_t)NNODES * HDIM];  // pong
__device__ float  g_dinv[NNODES];
__device__ int    g_deg[NNODES];
__device__ int    g_off[NNODES + 1];
__device__ int    g_cur[NNODES];
__device__ int    g_csr[EEDGES];
__device__ int    g_bsum[NSCAN];
__device__ int    g_bbase[NSCAN];
__device__ __half g_Wt[3][2][128 * 128];          // k-major W, fp16 hi/lo split

// ---------------------------------------------------------------------------
__device__ __forceinline__ uint32_t smem_u32(const void* p) {
    uint32_t a;
    asm("{ .reg .u64 t; cvta.to.shared.u64 t, %1; cvt.u32.u64 %0, t; }"
        : "=r"(a) : "l"(p));
    return a;
}

#define LDSM_X4(r, a) \
    asm volatile("ldmatrix.sync.aligned.m8n8.x4.shared.b16 {%0,%1,%2,%3}, [%4];" \
                 : "=r"((r)[0]), "=r"((r)[1]), "=r"((r)[2]), "=r"((r)[3]) : "r"(a))
#define LDSM_X4T(r, a) \
    asm volatile("ldmatrix.sync.aligned.m8n8.x4.trans.shared.b16 {%0,%1,%2,%3}, [%4];" \
                 : "=r"((r)[0]), "=r"((r)[1]), "=r"((r)[2]), "=r"((r)[3]) : "r"(a))
#define MMA_F16(c, a, b0, b1) \
    asm volatile("mma.sync.aligned.m16n8k16.row.col.f32.f16.f16.f32 " \
                 "{%0,%1,%2,%3}, {%4,%5,%6,%7}, {%8,%9}, {%0,%1,%2,%3};" \
                 : "+f"((c)[0]), "+f"((c)[1]), "+f"((c)[2]), "+f"((c)[3]) \
                 : "r"((a)[0]), "r"((a)[1]), "r"((a)[2]), "r"((a)[3]), \
                   "r"(b0), "r"(b1))

// ---------------------------------------------------------------------------
// Degree / CSR build
// ---------------------------------------------------------------------------
__global__ void deg_count(const int* __restrict__ dst) {
    int e = blockIdx.x * blockDim.x + threadIdx.x;
    if (e < EEDGES) atomicAdd(&g_deg[dst[e]], 1);
}
// scan1 also computes dinv = rsqrt(deg+1)
__global__ __launch_bounds__(SCAN_T)
void scan1() {
    __shared__ int sh[SCAN_T];
    int b = blockIdx.x, t = threadIdx.x;
    int base = b * SCAN_BLK + t * 4;
    int v[4];
#pragma unroll
    for (int j = 0; j < 4; j++) {
        int i = base + j;
        v[j] = (i < NNODES) ? g_deg[i] : 0;
        if (i < NNODES) g_dinv[i] = rsqrtf((float)v[j] + 1.0f);
    }
    int tot = v[0] + v[1] + v[2] + v[3];
    sh[t] = tot;
    __syncthreads();
    for (int o = 1; o < SCAN_T; o <<= 1) {
        int x = 0;
        if (t >= o) x = sh[t - o];
        __syncthreads();
        sh[t] += x;
        __syncthreads();
    }
    int run = sh[t] - tot;
#pragma unroll
    for (int j = 0; j < 4; j++) {
        int i = base + j;
        if (i < NNODES) g_off[i] = run;
        run += v[j];
    }
    if (t == SCAN_T - 1) g_bsum[b] = sh[t];
}
__global__ void scan2p() {
    __shared__ int sh[128];
    int t = threadIdx.x;
    int v = (t < NSCAN) ? g_bsum[t] : 0;
    sh[t] = v;
    __syncthreads();
    for (int o = 1; o < 128; o <<= 1) {
        int x = 0;
        if (t >= o) x = sh[t - o];
        __syncthreads();
        sh[t] += x;
        __syncthreads();
    }
    if (t < NSCAN) g_bbase[t] = sh[t] - v;
    if (t == 127) g_off[NNODES] = sh[127];
}
__global__ void scan3() {
    int i = blockIdx.x * blockDim.x + threadIdx.x;
    if (i < NNODES) {
        int v = g_off[i] + g_bbase[i / SCAN_BLK];
        g_off[i] = v;
        g_cur[i] = v;
    }
}
__global__ void csr_fill(const int* __restrict__ src, const int* __restrict__ dst) {
    int e = blockIdx.x * blockDim.x + threadIdx.x;
    if (e < EEDGES) {
        int d = dst[e];
        int slot = atomicAdd(&g_cur[d], 1);
        g_csr[slot] = src[e];
    }
}

// ---------------------------------------------------------------------------
// Prep: split W (k-major, [k][n]) into fp16 hi/lo (near-exact sum).
// ---------------------------------------------------------------------------
__global__ void prep_w(const float* __restrict__ W0, const float* __restrict__ W1,
                       const float* __restrict__ W2) {
    int idx = blockIdx.x * blockDim.x + threadIdx.x;
    if (idx >= 3 * 16384) return;
    int l = idx >> 14;
    int e = idx & 16383;
    const float* W = (l == 0) ? W0 : (l == 1) ? W1 : W2;
    float v = W[e];
    __half hi = __float2half_rn(v);
    __half lo = __float2half_rn(v - __half2float(hi));
    g_Wt[l][0][e] = hi;
    g_Wt[l][1][e] = lo;
}

// ---------------------------------------------------------------------------
// GEMM device helpers
// ---------------------------------------------------------------------------
__device__ __forceinline__ void fill_w_tiles(char* sm, uint32_t woff, int wl,
                                             int tid) {
    const uint4* whi = (const uint4*)g_Wt[wl][0];
    const uint4* wlo = (const uint4*)g_Wt[wl][1];
#pragma unroll
    for (int i = tid; i < 2048; i += 512) {
        int r  = i >> 4;
        int c4 = i & 15;
        uint32_t off = (uint32_t)r * (PADH * 2) + c4 * 16;
        *(uint4*)(sm + woff + off)         = __ldg(&whi[i]);
        *(uint4*)(sm + woff + TILEB + off) = __ldg(&wlo[i]);
    }
}

template <bool DUAL_A, bool SCALE>
__device__ __forceinline__ void mma_and_store(uint32_t uA, uint32_t uWhi,
                                              int wid, int lane, int bm,
                                              const float* dinv,
                                              __half* __restrict__ C16) {
    const uint32_t uWlo = uWhi + TILEB;
    const int mt = wid >> 1;
    const int nh = wid & 1;
    const int lr = lane & 15;
    const int lc = lane >> 4;

    float acc[8][4];
#pragma unroll
    for (int j = 0; j < 8; j++)
#pragma unroll
        for (int q = 0; q < 4; q++) acc[j][q] = 0.0f;

#pragma unroll
    for (int ks = 0; ks < 8; ks++) {
        uint32_t aoff = (uint32_t)(mt * 16 + lr) * (PADH * 2) + (ks * 16 + lc * 8) * 2;
        uint32_t aH[4], aL[4];
        LDSM_X4(aH, uA + aoff);
        if (DUAL_A) LDSM_X4(aL, uA + TILEB + aoff);

        uint32_t brow = (uint32_t)(ks * 16 + lr) * (PADH * 2);
#pragma unroll
        for (int p = 0; p < 4; p++) {
            uint32_t boff = brow + (nh * 64 + p * 16 + lc * 8) * 2;
            uint32_t bH[4], bL[4];
            LDSM_X4T(bH, uWhi + boff);
            LDSM_X4T(bL, uWlo + boff);
            MMA_F16(acc[2 * p],     aH, bH[0], bH[1]);
            MMA_F16(acc[2 * p + 1], aH, bH[2], bH[3]);
            MMA_F16(acc[2 * p],     aH, bL[0], bL[1]);
            MMA_F16(acc[2 * p + 1], aH, bL[2], bL[3]);
            if (DUAL_A) {
                MMA_F16(acc[2 * p],     aL, bH[0], bH[1]);
                MMA_F16(acc[2 * p + 1], aL, bH[2], bH[3]);
            }
        }
    }

    int row0 = bm + mt * 16 + (lane >> 2);
    int row1 = row0 + 8;
    float s0 = 1.f, s1 = 1.f;
    if (SCALE) {
        s0 = (row0 < NNODES) ? __ldg(&dinv[row0]) : 0.f;
        s1 = (row1 < NNODES) ? __ldg(&dinv[row1]) : 0.f;
    }
    int colb = nh * 64 + (lane & 3) * 2;
    if (row0 < NNODES) {
        __half* o = &C16[(size_t)row0 * 128 + colb];
#pragma unroll
        for (int j = 0; j < 8; j++)
            *(__half2*)(o + j * 8) = __floats2half2_rn(acc[j][0] * s0, acc[j][1] * s0);
    }
    if (row1 < NNODES) {
        __half* o = &C16[(size_t)row1 * 128 + colb];
#pragma unroll
        for (int j = 0; j < 8; j++)
            *(__half2*)(o + j * 8) = __floats2half2_rn(acc[j][2] * s1, acc[j][3] * s1);
    }
}

// ---------------------------------------------------------------------------
// Layer-0 GEMM (fp32 A, fp16 hi/lo split, NO dinv): h16 = fp16( x @ W0 )
// ---------------------------------------------------------------------------
__global__ __launch_bounds__(512, 1)
void gemm_f32(const float* __restrict__ A, __half* __restrict__ C16) {
    extern __shared__ char sm[];
    const int tid  = threadIdx.x;
    const int wid  = tid >> 5;
    const int lane = tid & 31;
    const int bm   = blockIdx.x * MTILE;
    const uint32_t uBase = smem_u32(sm);

    fill_w_tiles(sm, 2 * TILEB, 0, tid);

#pragma unroll
    for (int idx = tid; idx < MTILE * 32; idx += 512) {
        int r  = idx >> 5;
        int c4 = idx & 31;
        int row = bm + r;
        float4 v = make_float4(0.f, 0.f, 0.f, 0.f);
        if (row < NNODES)
            v = *(const float4*)&A[(size_t)row * 128 + c4 * 4];
        __half h0 = __float2half_rn(v.x), h1 = __float2half_rn(v.y);
        __half h2 = __float2half_rn(v.z), h3 = __float2half_rn(v.w);
        __half l0 = __float2half_rn(v.x - __half2float(h0));
        __half l1 = __float2half_rn(v.y - __half2float(h1));
        __half l2 = __float2half_rn(v.z - __half2float(h2));
        __half l3 = __float2half_rn(v.w - __half2float(h3));
        uint32_t off = (uint32_t)r * (PADH * 2) + c4 * 8;
        *(__half2*)(sm + off)             = __halves2half2(h0, h1);
        *(__half2*)(sm + off + 4)         = __halves2half2(h2, h3);
        *(__half2*)(sm + TILEB + off)     = __halves2half2(l0, l1);
        *(__half2*)(sm + TILEB + off + 4) = __halves2half2(l2, l3);
    }
    __syncthreads();

    mma_and_store<true, false>(uBase, uBase + 2 * TILEB, wid, lane, bm, nullptr, C16);
}

// ---------------------------------------------------------------------------
// Layers 1..2 GEMM (fp16 A, exact): out = fp16( dinv*(A@W) )
// ---------------------------------------------------------------------------
__global__ __launch_bounds__(512, 2)
void gemm_f16(const __half* __restrict__ A16, int wl,
              const float* __restrict__ dinv, __half* __restrict__ C16) {
    extern __shared__ char sm[];
    const int tid  = threadIdx.x;
    const int wid  = tid >> 5;
    const int lane = tid & 31;
    const int bm   = blockIdx.x * MTILE;
    const uint32_t uBase = smem_u32(sm);

    fill_w_tiles(sm, TILEB, wl, tid);

    const uint2* ap = (const uint2*)A16;
#pragma unroll
    for (int idx = tid; idx < MTILE * 32; idx += 512) {
        int r  = idx >> 5;
        int c4 = idx & 31;
        int row = bm + r;
        uint2 u = make_uint2(0u, 0u);
        if (row < NNODES) u = __ldg(&ap[(size_t)row * 32 + c4]);
        uint32_t off = (uint32_t)r * (PADH * 2) + c4 * 8;
        *(uint2*)(sm + off) = u;
    }
    __syncthreads();

    mma_and_store<false, true>(uBase, uBase + TILEB, wid, lane, bm, dinv, C16);
}

// ---------------------------------------------------------------------------
// Gather: one warp per node (R9 body: 8-deep unroll + scalar tail).
// 64-thread blocks (2 warps) to cut CTA-retirement tail waste from degree
// variance. SRC_SCALED: h already carries dinv[src]. FINAL_F32: write fp32.
// ---------------------------------------------------------------------------
#define ACCW(u, wgt) { \
    float2 _a = __half22float2(*(const __half2*)&(u).x); \
    float2 _b = __half22float2(*(const __half2*)&(u).y); \
    acc.x += _a.x * (wgt); acc.y += _a.y * (wgt); \
    acc.z += _b.x * (wgt); acc.w += _b.y * (wgt); }

template <bool SRC_SCALED, bool FINAL_F32>
__global__ __launch_bounds__(GBLK)
void gather_k(const __half* __restrict__ hs, const float* __restrict__ bias,
              void* __restrict__ outv) {
    int w = (int)((blockIdx.x * (unsigned)GBLK + threadIdx.x) >> 5);
    if (w >= NNODES) return;
    int lane = threadIdx.x & 31;
    const uint2* hp = (const uint2*)hs;

    int e    = g_off[w];
    int eend = g_off[w + 1];
    float sc = __ldg(&g_dinv[w]);

    float4 acc = make_float4(0.f, 0.f, 0.f, 0.f);
    {
        uint2 u = __ldg(&hp[w * 32 + lane]);
        float wgt = SRC_SCALED ? 1.f : sc;
        ACCW(u, wgt)
    }

    for (; e + 8 <= eend; e += 8) {
        int s0 = __ldg(&g_csr[e + 0]);
        int s1 = __ldg(&g_csr[e + 1]);
        int s2 = __ldg(&g_csr[e + 2]);
        int s3 = __ldg(&g_csr[e + 3]);
        int s4 = __ldg(&g_csr[e + 4]);
        int s5 = __ldg(&g_csr[e + 5]);
        int s6 = __ldg(&g_csr[e + 6]);
        int s7 = __ldg(&g_csr[e + 7]);
        uint2 u0 = __ldg(&hp[s0 * 32 + lane]);
        uint2 u1 = __ldg(&hp[s1 * 32 + lane]);
        uint2 u2 = __ldg(&hp[s2 * 32 + lane]);
        uint2 u3 = __ldg(&hp[s3 * 32 + lane]);
        uint2 u4 = __ldg(&hp[s4 * 32 + lane]);
        uint2 u5 = __ldg(&hp[s5 * 32 + lane]);
        uint2 u6 = __ldg(&hp[s6 * 32 + lane]);
        uint2 u7 = __ldg(&hp[s7 * 32 + lane]);
        if (SRC_SCALED) {
            ACCW(u0, 1.f) ACCW(u1, 1.f) ACCW(u2, 1.f) ACCW(u3, 1.f)
            ACCW(u4, 1.f) ACCW(u5, 1.f) ACCW(u6, 1.f) ACCW(u7, 1.f)
        } else {
            ACCW(u0, __ldg(&g_dinv[s0])) ACCW(u1, __ldg(&g_dinv[s1]))
            ACCW(u2, __ldg(&g_dinv[s2])) ACCW(u3, __ldg(&g_dinv[s3]))
            ACCW(u4, __ldg(&g_dinv[s4])) ACCW(u5, __ldg(&g_dinv[s5]))
            ACCW(u6, __ldg(&g_dinv[s6])) ACCW(u7, __ldg(&g_dinv[s7]))
        }
    }
    for (; e < eend; e++) {
        int s = __ldg(&g_csr[e]);
        uint2 u = __ldg(&hp[s * 32 + lane]);
        float wgt = SRC_SCALED ? 1.f : __ldg(&g_dinv[s]);
        ACCW(u, wgt)
    }

    float4 bb = *(const float4*)&bias[lane * 4];
    acc.x = fmaxf(acc.x * sc + bb.x, 0.f);
    acc.y = fmaxf(acc.y * sc + bb.y, 0.f);
    acc.z = fmaxf(acc.z * sc + bb.z, 0.f);
    acc.w = fmaxf(acc.w * sc + bb.w, 0.f);

    if (FINAL_F32) {
        ((float4*)outv)[w * 32 + lane] = acc;
    } else {
        __half2 o0 = __floats2half2_rn(acc.x, acc.y);
        __half2 o1 = __floats2half2_rn(acc.z, acc.w);
        uint2 ou;
        ou.x = *(const uint32_t*)&o0;
        ou.y = *(const uint32_t*)&o1;
        ((uint2*)outv)[w * 32 + lane] = ou;
    }
}
#undef ACCW

// ---------------------------------------------------------------------------
extern "C" void kernel_launch(void* const* d_in, const int* in_sizes, int n_in,
                              void* d_out, int out_size) {
    const float* x  = (const float*)d_in[0];
    const int*   ei = (const int*)d_in[1];
    const float* W0 = (const float*)d_in[2];
    const float* b0 = (const float*)d_in[3];
    const float* W1 = (const float*)d_in[4];
    const float* b1 = (const float*)d_in[5];
    const float* W2 = (const float*)d_in[6];
    const float* b2 = (const float*)d_in[7];
    const int* src = ei;
    const int* dst = ei + EEDGES;

    __half *ha, *hb;
    float* dinv;
    int*   deg;
    cudaGetSymbolAddress((void**)&ha, g_h16a);
    cudaGetSymbolAddress((void**)&hb, g_h16b);
    cudaGetSymbolAddress((void**)&dinv, g_dinv);
    cudaGetSymbolAddress((void**)&deg,  g_deg);

    cudaFuncSetAttribute(gemm_f32, cudaFuncAttributeMaxDynamicSharedMemorySize, SMEM_L0);
    cudaFuncSetAttribute(gemm_f16, cudaFuncAttributeMaxDynamicSharedMemorySize, SMEM_F16);

    static cudaStream_t s2 = nullptr;
    static cudaEvent_t evFork = nullptr, evJoin = nullptr;
    if (!s2) {
        cudaStreamCreateWithFlags(&s2, cudaStreamNonBlocking);
        cudaEventCreateWithFlags(&evFork, cudaEventDisableTiming);
        cudaEventCreateWithFlags(&evJoin, cudaEventDisableTiming);
    }

    // Fork: side stream does W prep + layer-0 GEMM (independent of CSR chain)
    cudaEventRecord(evFork, 0);
    cudaStreamWaitEvent(s2, evFork, 0);
    prep_w<<<(3 * 16384 + 255) / 256, 256, 0, s2>>>(W0, W1, W2);
    gemm_f32<<<NTILES, 512, SMEM_L0, s2>>>(x, ha);
    cudaEventRecord(evJoin, s2);

    // Main stream: degree + CSR build
    cudaMemsetAsync(deg, 0, NNODES * sizeof(int), 0);
    deg_count<<<(EEDGES + 255) / 256, 256>>>(dst);
    scan1<<<NSCAN, SCAN_T>>>();
    scan2p<<<1, 128>>>();
    scan3<<<(NNODES + 255) / 256, 256>>>();
    csr_fill<<<(EEDGES + 255) / 256, 256>>>(src, dst);

    // Join, then the serial layer chain
    cudaStreamWaitEvent(0, evJoin, 0);

    const int gather_blocks = (NNODES * 32 + GBLK - 1) / GBLK;
    gather_k<false, false><<<gather_blocks, GBLK>>>(ha, b0, hb);
    gemm_f16<<<NTILES, 512, SMEM_F16>>>(hb, 1, dinv, ha);
    gather_k<true, false><<<gather_blocks, GBLK>>>(ha, b1, hb);
    gemm_f16<<<NTILES, 512, SMEM_F16>>>(hb, 2, dinv, ha);
    gather_k<true, true><<<gather_blocks, GBLK>>>(ha, b2, d_out);
}

// round 15
// speedup vs baseline: 1.2258x; 1.0669x over previous
#include <cuda_runtime.h>
#include <cuda_fp16.h>
#include <cstdint>

#define NNODES 100000
#define EEDGES 1600000
#define HDIM   128

#define SCAN_BLK 1024
#define SCAN_T   256
#define NSCAN    ((NNODES + SCAN_BLK - 1) / SCAN_BLK)   // 98

#define MTILE   128
#define NTILES  ((NNODES + MTILE - 1) / MTILE)          // 782
#define PADH    136                                      // halves per padded row (272 B)
#define TILEB   (128 * PADH * 2)                         // 34816 B per fp16 tile
#define SMEM_L0 (4 * TILEB)                              // A_hi, A_lo, W_hi, W_lo
#define SMEM_F16 (2 * TILEB)                             // A, W_hi (Wlo dropped)

// ---------------------------------------------------------------------------
// Scratch (device globals)
// ---------------------------------------------------------------------------
__device__ __half g_h16a[(size_t)NNODES * HDIM];  // ping
__device__ __half g_h16b[(size_t)NNODES * HDIM];  // pong
__device__ float  g_dinv[NNODES];
__device__ int    g_deg[NNODES];
__device__ int    g_off[NNODES + 1];
__device__ int    g_cur[NNODES];
__device__ int    g_csr[EEDGES];
__device__ int    g_bsum[NSCAN];
__device__ int    g_bbase[NSCAN];
__device__ __half g_Wt[3][2][128 * 128];          // k-major W, fp16 hi/lo split

// ---------------------------------------------------------------------------
__device__ __forceinline__ uint32_t smem_u32(const void* p) {
    uint32_t a;
    asm("{ .reg .u64 t; cvta.to.shared.u64 t, %1; cvt.u32.u64 %0, t; }"
        : "=r"(a) : "l"(p));
    return a;
}

#define LDSM_X4(r, a) \
    asm volatile("ldmatrix.sync.aligned.m8n8.x4.shared.b16 {%0,%1,%2,%3}, [%4];" \
                 : "=r"((r)[0]), "=r"((r)[1]), "=r"((r)[2]), "=r"((r)[3]) : "r"(a))
#define LDSM_X4T(r, a) \
    asm volatile("ldmatrix.sync.aligned.m8n8.x4.trans.shared.b16 {%0,%1,%2,%3}, [%4];" \
                 : "=r"((r)[0]), "=r"((r)[1]), "=r"((r)[2]), "=r"((r)[3]) : "r"(a))
#define MMA_F16(c, a, b0, b1) \
    asm volatile("mma.sync.aligned.m16n8k16.row.col.f32.f16.f16.f32 " \
                 "{%0,%1,%2,%3}, {%4,%5,%6,%7}, {%8,%9}, {%0,%1,%2,%3};" \
                 : "+f"((c)[0]), "+f"((c)[1]), "+f"((c)[2]), "+f"((c)[3]) \
                 : "r"((a)[0]), "r"((a)[1]), "r"((a)[2]), "r"((a)[3]), \
                   "r"(b0), "r"(b1))

// ---------------------------------------------------------------------------
// Degree / CSR build
// ---------------------------------------------------------------------------
__global__ void deg_count(const int* __restrict__ dst) {
    int e = blockIdx.x * blockDim.x + threadIdx.x;
    if (e < EEDGES) atomicAdd(&g_deg[dst[e]], 1);
}
// scan1 also computes dinv = rsqrt(deg+1)
__global__ __launch_bounds__(SCAN_T)
void scan1() {
    __shared__ int sh[SCAN_T];
    int b = blockIdx.x, t = threadIdx.x;
    int base = b * SCAN_BLK + t * 4;
    int v[4];
#pragma unroll
    for (int j = 0; j < 4; j++) {
        int i = base + j;
        v[j] = (i < NNODES) ? g_deg[i] : 0;
        if (i < NNODES) g_dinv[i] = rsqrtf((float)v[j] + 1.0f);
    }
    int tot = v[0] + v[1] + v[2] + v[3];
    sh[t] = tot;
    __syncthreads();
    for (int o = 1; o < SCAN_T; o <<= 1) {
        int x = 0;
        if (t >= o) x = sh[t - o];
        __syncthreads();
        sh[t] += x;
        __syncthreads();
    }
    int run = sh[t] - tot;
#pragma unroll
    for (int j = 0; j < 4; j++) {
        int i = base + j;
        if (i < NNODES) g_off[i] = run;
        run += v[j];
    }
    if (t == SCAN_T - 1) g_bsum[b] = sh[t];
}
__global__ void scan2p() {
    __shared__ int sh[128];
    int t = threadIdx.x;
    int v = (t < NSCAN) ? g_bsum[t] : 0;
    sh[t] = v;
    __syncthreads();
    for (int o = 1; o < 128; o <<= 1) {
        int x = 0;
        if (t >= o) x = sh[t - o];
        __syncthreads();
        sh[t] += x;
        __syncthreads();
    }
    if (t < NSCAN) g_bbase[t] = sh[t] - v;
    if (t == 127) g_off[NNODES] = sh[127];
}
__global__ void scan3() {
    int i = blockIdx.x * blockDim.x + threadIdx.x;
    if (i < NNODES) {
        int v = g_off[i] + g_bbase[i / SCAN_BLK];
        g_off[i] = v;
        g_cur[i] = v;
    }
}
__global__ void csr_fill(const int* __restrict__ src, const int* __restrict__ dst) {
    int e = blockIdx.x * blockDim.x + threadIdx.x;
    if (e < EEDGES) {
        int d = dst[e];
        int slot = atomicAdd(&g_cur[d], 1);
        g_csr[slot] = src[e];
    }
}

// ---------------------------------------------------------------------------
// Prep: split W (k-major, [k][n]) into fp16 hi/lo (near-exact sum).
// ---------------------------------------------------------------------------
__global__ void prep_w(const float* __restrict__ W0, const float* __restrict__ W1,
                       const float* __restrict__ W2) {
    int idx = blockIdx.x * blockDim.x + threadIdx.x;
    if (idx >= 3 * 16384) return;
    int l = idx >> 14;
    int e = idx & 16383;
    const float* W = (l == 0) ? W0 : (l == 1) ? W1 : W2;
    float v = W[e];
    __half hi = __float2half_rn(v);
    __half lo = __float2half_rn(v - __half2float(hi));
    g_Wt[l][0][e] = hi;
    g_Wt[l][1][e] = lo;
}

// ---------------------------------------------------------------------------
// GEMM device helpers
// ---------------------------------------------------------------------------
// Copy W tiles into smem at byte offset woff (hi; + lo at woff+TILEB if LO).
template <bool LO>
__device__ __forceinline__ void fill_w_tiles(char* sm, uint32_t woff, int wl,
                                             int tid) {
    const uint4* whi = (const uint4*)g_Wt[wl][0];
    const uint4* wlo = (const uint4*)g_Wt[wl][1];
#pragma unroll
    for (int i = tid; i < 2048; i += 512) {
        int r  = i >> 4;
        int c4 = i & 15;
        uint32_t off = (uint32_t)r * (PADH * 2) + c4 * 16;
        *(uint4*)(sm + woff + off) = __ldg(&whi[i]);
        if (LO) *(uint4*)(sm + woff + TILEB + off) = __ldg(&wlo[i]);
    }
}

// MMA core. DUAL_A: A_lo tile at uA+TILEB adds Alo*Whi.
// DUAL_B: W_lo tile at uWhi+TILEB adds Ahi*Wlo. SCALE: dinv[row] epilogue.
template <bool DUAL_A, bool DUAL_B, bool SCALE>
__device__ __forceinline__ void mma_and_store(uint32_t uA, uint32_t uWhi,
                                              int wid, int lane, int bm,
                                              const float* dinv,
                                              __half* __restrict__ C16) {
    const uint32_t uWlo = uWhi + TILEB;
    const int mt = wid >> 1;
    const int nh = wid & 1;
    const int lr = lane & 15;
    const int lc = lane >> 4;

    float acc[8][4];
#pragma unroll
    for (int j = 0; j < 8; j++)
#pragma unroll
        for (int q = 0; q < 4; q++) acc[j][q] = 0.0f;

#pragma unroll
    for (int ks = 0; ks < 8; ks++) {
        uint32_t aoff = (uint32_t)(mt * 16 + lr) * (PADH * 2) + (ks * 16 + lc * 8) * 2;
        uint32_t aH[4], aL[4];
        LDSM_X4(aH, uA + aoff);
        if (DUAL_A) LDSM_X4(aL, uA + TILEB + aoff);

        uint32_t brow = (uint32_t)(ks * 16 + lr) * (PADH * 2);
#pragma unroll
        for (int p = 0; p < 4; p++) {
            uint32_t boff = brow + (nh * 64 + p * 16 + lc * 8) * 2;
            uint32_t bH[4];
            LDSM_X4T(bH, uWhi + boff);
            MMA_F16(acc[2 * p],     aH, bH[0], bH[1]);
            MMA_F16(acc[2 * p + 1], aH, bH[2], bH[3]);
            if (DUAL_B) {
                uint32_t bL[4];
                LDSM_X4T(bL, uWlo + boff);
                MMA_F16(acc[2 * p],     aH, bL[0], bL[1]);
                MMA_F16(acc[2 * p + 1], aH, bL[2], bL[3]);
            }
            if (DUAL_A) {
                MMA_F16(acc[2 * p],     aL, bH[0], bH[1]);
                MMA_F16(acc[2 * p + 1], aL, bH[2], bH[3]);
            }
        }
    }

    int row0 = bm + mt * 16 + (lane >> 2);
    int row1 = row0 + 8;
    float s0 = 1.f, s1 = 1.f;
    if (SCALE) {
        s0 = (row0 < NNODES) ? __ldg(&dinv[row0]) : 0.f;
        s1 = (row1 < NNODES) ? __ldg(&dinv[row1]) : 0.f;
    }
    int colb = nh * 64 + (lane & 3) * 2;
    if (row0 < NNODES) {
        __half* o = &C16[(size_t)row0 * 128 + colb];
#pragma unroll
        for (int j = 0; j < 8; j++)
            *(__half2*)(o + j * 8) = __floats2half2_rn(acc[j][0] * s0, acc[j][1] * s0);
    }
    if (row1 < NNODES) {
        __half* o = &C16[(size_t)row1 * 128 + colb];
#pragma unroll
        for (int j = 0; j < 8; j++)
            *(__half2*)(o + j * 8) = __floats2half2_rn(acc[j][2] * s1, acc[j][3] * s1);
    }
}

// ---------------------------------------------------------------------------
// Layer-0 GEMM (fp32 A, full 3-term split; off critical path): h16 = x @ W0
// ---------------------------------------------------------------------------
__global__ __launch_bounds__(512, 1)
void gemm_f32(const float* __restrict__ A, __half* __restrict__ C16) {
    extern __shared__ char sm[];
    const int tid  = threadIdx.x;
    const int wid  = tid >> 5;
    const int lane = tid & 31;
    const int bm   = blockIdx.x * MTILE;
    const uint32_t uBase = smem_u32(sm);

    fill_w_tiles<true>(sm, 2 * TILEB, 0, tid);

#pragma unroll
    for (int idx = tid; idx < MTILE * 32; idx += 512) {
        int r  = idx >> 5;
        int c4 = idx & 31;
        int row = bm + r;
        float4 v = make_float4(0.f, 0.f, 0.f, 0.f);
        if (row < NNODES)
            v = *(const float4*)&A[(size_t)row * 128 + c4 * 4];
        __half h0 = __float2half_rn(v.x), h1 = __float2half_rn(v.y);
        __half h2 = __float2half_rn(v.z), h3 = __float2half_rn(v.w);
        __half l0 = __float2half_rn(v.x - __half2float(h0));
        __half l1 = __float2half_rn(v.y - __half2float(h1));
        __half l2 = __float2half_rn(v.z - __half2float(h2));
        __half l3 = __float2half_rn(v.w - __half2float(h3));
        uint32_t off = (uint32_t)r * (PADH * 2) + c4 * 8;
        *(__half2*)(sm + off)             = __halves2half2(h0, h1);
        *(__half2*)(sm + off + 4)         = __halves2half2(h2, h3);
        *(__half2*)(sm + TILEB + off)     = __halves2half2(l0, l1);
        *(__half2*)(sm + TILEB + off + 4) = __halves2half2(l2, l3);
    }
    __syncthreads();

    mma_and_store<true, true, false>(uBase, uBase + 2 * TILEB, wid, lane, bm,
                                     nullptr, C16);
}

// ---------------------------------------------------------------------------
// Layers 1..2 GEMM (fp16 A exact, W_hi only — critical path, halved MMAs):
//   out = fp16( dinv*(A@Whi) )
// ---------------------------------------------------------------------------
__global__ __launch_bounds__(512, 2)
void gemm_f16(const __half* __restrict__ A16, int wl,
              const float* __restrict__ dinv, __half* __restrict__ C16) {
    extern __shared__ char sm[];
    const int tid  = threadIdx.x;
    const int wid  = tid >> 5;
    const int lane = tid & 31;
    const int bm   = blockIdx.x * MTILE;
    const uint32_t uBase = smem_u32(sm);

    fill_w_tiles<false>(sm, TILEB, wl, tid);

    const uint2* ap = (const uint2*)A16;
#pragma unroll
    for (int idx = tid; idx < MTILE * 32; idx += 512) {
        int r  = idx >> 5;
        int c4 = idx & 31;
        int row = bm + r;
        uint2 u = make_uint2(0u, 0u);
        if (row < NNODES) u = __ldg(&ap[(size_t)row * 32 + c4]);
        uint32_t off = (uint32_t)r * (PADH * 2) + c4 * 8;
        *(uint2*)(sm + off) = u;
    }
    __syncthreads();

    mma_and_store<false, false, true>(uBase, uBase + TILEB, wid, lane, bm,
                                      dinv, C16);
}

// ---------------------------------------------------------------------------
// Gather: one warp per node (R9-optimal body: 8-deep unroll + scalar tail).
// SRC_SCALED: h already carries dinv[src]. FINAL_F32: write fp32.
// ---------------------------------------------------------------------------
#define ACCW(u, wgt) { \
    float2 _a = __half22float2(*(const __half2*)&(u).x); \
    float2 _b = __half22float2(*(const __half2*)&(u).y); \
    acc.x += _a.x * (wgt); acc.y += _a.y * (wgt); \
    acc.z += _b.x * (wgt); acc.w += _b.y * (wgt); }

template <bool SRC_SCALED, bool FINAL_F32>
__global__ __launch_bounds__(256)
void gather_k(const __half* __restrict__ hs, const float* __restrict__ bias,
              void* __restrict__ outv) {
    int w = (int)((blockIdx.x * (unsigned)blockDim.x + threadIdx.x) >> 5);
    if (w >= NNODES) return;
    int lane = threadIdx.x & 31;
    const uint2* hp = (const uint2*)hs;

    int e    = g_off[w];
    int eend = g_off[w + 1];
    float sc = __ldg(&g_dinv[w]);

    float4 acc = make_float4(0.f, 0.f, 0.f, 0.f);
    {
        uint2 u = __ldg(&hp[w * 32 + lane]);
        float wgt = SRC_SCALED ? 1.f : sc;
        ACCW(u, wgt)
    }

    for (; e + 8 <= eend; e += 8) {
        int s0 = __ldg(&g_csr[e + 0]);
        int s1 = __ldg(&g_csr[e + 1]);
        int s2 = __ldg(&g_csr[e + 2]);
        int s3 = __ldg(&g_csr[e + 3]);
        int s4 = __ldg(&g_csr[e + 4]);
        int s5 = __ldg(&g_csr[e + 5]);
        int s6 = __ldg(&g_csr[e + 6]);
        int s7 = __ldg(&g_csr[e + 7]);
        uint2 u0 = __ldg(&hp[s0 * 32 + lane]);
        uint2 u1 = __ldg(&hp[s1 * 32 + lane]);
        uint2 u2 = __ldg(&hp[s2 * 32 + lane]);
        uint2 u3 = __ldg(&hp[s3 * 32 + lane]);
        uint2 u4 = __ldg(&hp[s4 * 32 + lane]);
        uint2 u5 = __ldg(&hp[s5 * 32 + lane]);
        uint2 u6 = __ldg(&hp[s6 * 32 + lane]);
        uint2 u7 = __ldg(&hp[s7 * 32 + lane]);
        if (SRC_SCALED) {
            ACCW(u0, 1.f) ACCW(u1, 1.f) ACCW(u2, 1.f) ACCW(u3, 1.f)
            ACCW(u4, 1.f) ACCW(u5, 1.f) ACCW(u6, 1.f) ACCW(u7, 1.f)
        } else {
            ACCW(u0, __ldg(&g_dinv[s0])) ACCW(u1, __ldg(&g_dinv[s1]))
            ACCW(u2, __ldg(&g_dinv[s2])) ACCW(u3, __ldg(&g_dinv[s3]))
            ACCW(u4, __ldg(&g_dinv[s4])) ACCW(u5, __ldg(&g_dinv[s5]))
            ACCW(u6, __ldg(&g_dinv[s6])) ACCW(u7, __ldg(&g_dinv[s7]))
        }
    }
    for (; e < eend; e++) {
        int s = __ldg(&g_csr[e]);
        uint2 u = __ldg(&hp[s * 32 + lane]);
        float wgt = SRC_SCALED ? 1.f : __ldg(&g_dinv[s]);
        ACCW(u, wgt)
    }

    float4 bb = *(const float4*)&bias[lane * 4];
    acc.x = fmaxf(acc.x * sc + bb.x, 0.f);
    acc.y = fmaxf(acc.y * sc + bb.y, 0.f);
    acc.z = fmaxf(acc.z * sc + bb.z, 0.f);
    acc.w = fmaxf(acc.w * sc + bb.w, 0.f);

    if (FINAL_F32) {
        ((float4*)outv)[w * 32 + lane] = acc;
    } else {
        __half2 o0 = __floats2half2_rn(acc.x, acc.y);
        __half2 o1 = __floats2half2_rn(acc.z, acc.w);
        uint2 ou;
        ou.x = *(const uint32_t*)&o0;
        ou.y = *(const uint32_t*)&o1;
        ((uint2*)outv)[w * 32 + lane] = ou;
    }
}
#undef ACCW

// ---------------------------------------------------------------------------
extern "C" void kernel_launch(void* const* d_in, const int* in_sizes, int n_in,
                              void* d_out, int out_size) {
    const float* x  = (const float*)d_in[0];
    const int*   ei = (const int*)d_in[1];
    const float* W0 = (const float*)d_in[2];
    const float* b0 = (const float*)d_in[3];
    const float* W1 = (const float*)d_in[4];
    const float* b1 = (const float*)d_in[5];
    const float* W2 = (const float*)d_in[6];
    const float* b2 = (const float*)d_in[7];
    const int* src = ei;
    const int* dst = ei + EEDGES;

    __half *ha, *hb;
    float* dinv;
    int*   deg;
    cudaGetSymbolAddress((void**)&ha, g_h16a);
    cudaGetSymbolAddress((void**)&hb, g_h16b);
    cudaGetSymbolAddress((void**)&dinv, g_dinv);
    cudaGetSymbolAddress((void**)&deg,  g_deg);

    cudaFuncSetAttribute(gemm_f32, cudaFuncAttributeMaxDynamicSharedMemorySize, SMEM_L0);
    cudaFuncSetAttribute(gemm_f16, cudaFuncAttributeMaxDynamicSharedMemorySize, SMEM_F16);

    static cudaStream_t s2 = nullptr;
    static cudaEvent_t evFork = nullptr, evJoin = nullptr;
    if (!s2) {
        cudaStreamCreateWithFlags(&s2, cudaStreamNonBlocking);
        cudaEventCreateWithFlags(&evFork, cudaEventDisableTiming);
        cudaEventCreateWithFlags(&evJoin, cudaEventDisableTiming);
    }

    // Fork: side stream does W prep + layer-0 GEMM (independent of CSR chain)
    cudaEventRecord(evFork, 0);
    cudaStreamWaitEvent(s2, evFork, 0);
    prep_w<<<(3 * 16384 + 255) / 256, 256, 0, s2>>>(W0, W1, W2);
    gemm_f32<<<NTILES, 512, SMEM_L0, s2>>>(x, ha);
    cudaEventRecord(evJoin, s2);

    // Main stream: degree + CSR build
    cudaMemsetAsync(deg, 0, NNODES * sizeof(int), 0);
    deg_count<<<(EEDGES + 255) / 256, 256>>>(dst);
    scan1<<<NSCAN, SCAN_T>>>();
    scan2p<<<1, 128>>>();
    scan3<<<(NNODES + 255) / 256, 256>>>();
    csr_fill<<<(EEDGES + 255) / 256, 256>>>(src, dst);

    // Join, then the serial layer chain
    cudaStreamWaitEvent(0, evJoin, 0);

    const int gather_blocks = (NNODES + 7) / 8;
    gather_k<false, false><<<gather_blocks, 256>>>(ha, b0, hb);
    gemm_f16<<<NTILES, 512, SMEM_F16>>>(hb, 1, dinv, ha);
    gather_k<true, false><<<gather_blocks, 256>>>(ha, b1, hb);
    gemm_f16<<<NTILES, 512, SMEM_F16>>>(hb, 2, dinv, ha);
    gather_k<true, true><<<gather_blocks, 256>>>(ha, b2, d_out);
}

// round 16
// speedup vs baseline: 1.2278x; 1.0016x over previous
#include <cuda_runtime.h>
#include <cuda_fp16.h>
#include <cstdint>

#define NNODES 100000
#define EEDGES 1600000
#define HDIM   128

#define SCAN_BLK 1024
#define SCAN_T   256
#define NSCAN    ((NNODES + SCAN_BLK - 1) / SCAN_BLK)   // 98

#define MTILE   128
#define NTILES  ((NNODES + MTILE - 1) / MTILE)          // 782
#define PADH    136                                      // halves per padded row (272 B)
#define TILEB   (128 * PADH * 2)                         // 34816 B per fp16 tile
#define SMEM_L0 (4 * TILEB)                              // A_hi, A_lo, W_hi, W_lo
#define SMEM_F16 (2 * TILEB)                             // A, W_hi (Wlo dropped)

// ---------------------------------------------------------------------------
// Scratch (device globals). g_deg invariant: zero at kernel_launch entry
// (BSS-zero initially; scan3 re-zeroes it each run for the next replay).
// ---------------------------------------------------------------------------
__device__ __half g_h16a[(size_t)NNODES * HDIM];  // ping
__device__ __half g_h16b[(size_t)NNODES * HDIM];  // pong
__device__ float  g_dinv[NNODES];
__device__ int    g_deg[NNODES];
__device__ int    g_off[NNODES + 1];
__device__ int    g_cur[NNODES];
__device__ int    g_csr[EEDGES];
__device__ int    g_bsum[NSCAN];
__device__ int    g_bbase[NSCAN];
__device__ __half g_Wt[3][2][128 * 128];          // k-major W, fp16 hi/lo split

// ---------------------------------------------------------------------------
__device__ __forceinline__ uint32_t smem_u32(const void* p) {
    uint32_t a;
    asm("{ .reg .u64 t; cvta.to.shared.u64 t, %1; cvt.u32.u64 %0, t; }"
        : "=r"(a) : "l"(p));
    return a;
}

#define LDSM_X4(r, a) \
    asm volatile("ldmatrix.sync.aligned.m8n8.x4.shared.b16 {%0,%1,%2,%3}, [%4];" \
                 : "=r"((r)[0]), "=r"((r)[1]), "=r"((r)[2]), "=r"((r)[3]) : "r"(a))
#define LDSM_X4T(r, a) \
    asm volatile("ldmatrix.sync.aligned.m8n8.x4.trans.shared.b16 {%0,%1,%2,%3}, [%4];" \
                 : "=r"((r)[0]), "=r"((r)[1]), "=r"((r)[2]), "=r"((r)[3]) : "r"(a))
#define MMA_F16(c, a, b0, b1) \
    asm volatile("mma.sync.aligned.m16n8k16.row.col.f32.f16.f16.f32 " \
                 "{%0,%1,%2,%3}, {%4,%5,%6,%7}, {%8,%9}, {%0,%1,%2,%3};" \
                 : "+f"((c)[0]), "+f"((c)[1]), "+f"((c)[2]), "+f"((c)[3]) \
                 : "r"((a)[0]), "r"((a)[1]), "r"((a)[2]), "r"((a)[3]), \
                   "r"(b0), "r"(b1))

// ---------------------------------------------------------------------------
// Degree / CSR build
// ---------------------------------------------------------------------------
// 4 edges per thread via int4.
__global__ void deg_count(const int* __restrict__ dst) {
    int t = blockIdx.x * blockDim.x + threadIdx.x;   // over EEDGES/4
    if (t < EEDGES / 4) {
        int4 d = ((const int4*)dst)[t];
        atomicAdd(&g_deg[d.x], 1);
        atomicAdd(&g_deg[d.y], 1);
        atomicAdd(&g_deg[d.z], 1);
        atomicAdd(&g_deg[d.w], 1);
    }
}
// scan1 also computes dinv = rsqrt(deg+1)
__global__ __launch_bounds__(SCAN_T)
void scan1() {
    __shared__ int sh[SCAN_T];
    int b = blockIdx.x, t = threadIdx.x;
    int base = b * SCAN_BLK + t * 4;
    int v[4];
#pragma unroll
    for (int j = 0; j < 4; j++) {
        int i = base + j;
        v[j] = (i < NNODES) ? g_deg[i] : 0;
        if (i < NNODES) g_dinv[i] = rsqrtf((float)v[j] + 1.0f);
    }
    int tot = v[0] + v[1] + v[2] + v[3];
    sh[t] = tot;
    __syncthreads();
    for (int o = 1; o < SCAN_T; o <<= 1) {
        int x = 0;
        if (t >= o) x = sh[t - o];
        __syncthreads();
        sh[t] += x;
        __syncthreads();
    }
    int run = sh[t] - tot;
#pragma unroll
    for (int j = 0; j < 4; j++) {
        int i = base + j;
        if (i < NNODES) g_off[i] = run;
        run += v[j];
    }
    if (t == SCAN_T - 1) g_bsum[b] = sh[t];
}
__global__ void scan2p() {
    __shared__ int sh[128];
    int t = threadIdx.x;
    int v = (t < NSCAN) ? g_bsum[t] : 0;
    sh[t] = v;
    __syncthreads();
    for (int o = 1; o < 128; o <<= 1) {
        int x = 0;
        if (t >= o) x = sh[t - o];
        __syncthreads();
        sh[t] += x;
        __syncthreads();
    }
    if (t < NSCAN) g_bbase[t] = sh[t] - v;
    if (t == 127) g_off[NNODES] = sh[127];
}
// scan3 also re-zeroes g_deg (restores the zero-on-entry invariant for the
// next graph replay; deg is dead after scan1).
__global__ void scan3() {
    int i = blockIdx.x * blockDim.x + threadIdx.x;
    if (i < NNODES) {
        int v = g_off[i] + g_bbase[i / SCAN_BLK];
        g_off[i] = v;
        g_cur[i] = v;
        g_deg[i] = 0;
    }
}
// 4 edges per thread via int4.
__global__ void csr_fill(const int* __restrict__ src, const int* __restrict__ dst) {
    int t = blockIdx.x * blockDim.x + threadIdx.x;   // over EEDGES/4
    if (t < EEDGES / 4) {
        int4 d = ((const int4*)dst)[t];
        int4 s = ((const int4*)src)[t];
        g_csr[atomicAdd(&g_cur[d.x], 1)] = s.x;
        g_csr[atomicAdd(&g_cur[d.y], 1)] = s.y;
        g_csr[atomicAdd(&g_cur[d.z], 1)] = s.z;
        g_csr[atomicAdd(&g_cur[d.w], 1)] = s.w;
    }
}

// ---------------------------------------------------------------------------
// Prep: split W (k-major, [k][n]) into fp16 hi/lo (near-exact sum).
// ---------------------------------------------------------------------------
__global__ void prep_w(const float* __restrict__ W0, const float* __restrict__ W1,
                       const float* __restrict__ W2) {
    int idx = blockIdx.x * blockDim.x + threadIdx.x;
    if (idx >= 3 * 16384) return;
    int l = idx >> 14;
    int e = idx & 16383;
    const float* W = (l == 0) ? W0 : (l == 1) ? W1 : W2;
    float v = W[e];
    __half hi = __float2half_rn(v);
    __half lo = __float2half_rn(v - __half2float(hi));
    g_Wt[l][0][e] = hi;
    g_Wt[l][1][e] = lo;
}

// ---------------------------------------------------------------------------
// GEMM device helpers
// ---------------------------------------------------------------------------
template <bool LO>
__device__ __forceinline__ void fill_w_tiles(char* sm, uint32_t woff, int wl,
                                             int tid) {
    const uint4* whi = (const uint4*)g_Wt[wl][0];
    const uint4* wlo = (const uint4*)g_Wt[wl][1];
#pragma unroll
    for (int i = tid; i < 2048; i += 512) {
        int r  = i >> 4;
        int c4 = i & 15;
        uint32_t off = (uint32_t)r * (PADH * 2) + c4 * 16;
        *(uint4*)(sm + woff + off) = __ldg(&whi[i]);
        if (LO) *(uint4*)(sm + woff + TILEB + off) = __ldg(&wlo[i]);
    }
}

template <bool DUAL_A, bool DUAL_B, bool SCALE>
__device__ __forceinline__ void mma_and_store(uint32_t uA, uint32_t uWhi,
                                              int wid, int lane, int bm,
                                              const float* dinv,
                                              __half* __restrict__ C16) {
    const uint32_t uWlo = uWhi + TILEB;
    const int mt = wid >> 1;
    const int nh = wid & 1;
    const int lr = lane & 15;
    const int lc = lane >> 4;

    float acc[8][4];
#pragma unroll
    for (int j = 0; j < 8; j++)
#pragma unroll
        for (int q = 0; q < 4; q++) acc[j][q] = 0.0f;

#pragma unroll
    for (int ks = 0; ks < 8; ks++) {
        uint32_t aoff = (uint32_t)(mt * 16 + lr) * (PADH * 2) + (ks * 16 + lc * 8) * 2;
        uint32_t aH[4], aL[4];
        LDSM_X4(aH, uA + aoff);
        if (DUAL_A) LDSM_X4(aL, uA + TILEB + aoff);

        uint32_t brow = (uint32_t)(ks * 16 + lr) * (PADH * 2);
#pragma unroll
        for (int p = 0; p < 4; p++) {
            uint32_t boff = brow + (nh * 64 + p * 16 + lc * 8) * 2;
            uint32_t bH[4];
            LDSM_X4T(bH, uWhi + boff);
            MMA_F16(acc[2 * p],     aH, bH[0], bH[1]);
            MMA_F16(acc[2 * p + 1], aH, bH[2], bH[3]);
            if (DUAL_B) {
                uint32_t bL[4];
                LDSM_X4T(bL, uWlo + boff);
                MMA_F16(acc[2 * p],     aH, bL[0], bL[1]);
                MMA_F16(acc[2 * p + 1], aH, bL[2], bL[3]);
            }
            if (DUAL_A) {
                MMA_F16(acc[2 * p],     aL, bH[0], bH[1]);
                MMA_F16(acc[2 * p + 1], aL, bH[2], bH[3]);
            }
        }
    }

    int row0 = bm + mt * 16 + (lane >> 2);
    int row1 = row0 + 8;
    float s0 = 1.f, s1 = 1.f;
    if (SCALE) {
        s0 = (row0 < NNODES) ? __ldg(&dinv[row0]) : 0.f;
        s1 = (row1 < NNODES) ? __ldg(&dinv[row1]) : 0.f;
    }
    int colb = nh * 64 + (lane & 3) * 2;
    if (row0 < NNODES) {
        __half* o = &C16[(size_t)row0 * 128 + colb];
#pragma unroll
        for (int j = 0; j < 8; j++)
            *(__half2*)(o + j * 8) = __floats2half2_rn(acc[j][0] * s0, acc[j][1] * s0);
    }
    if (row1 < NNODES) {
        __half* o = &C16[(size_t)row1 * 128 + colb];
#pragma unroll
        for (int j = 0; j < 8; j++)
            *(__half2*)(o + j * 8) = __floats2half2_rn(acc[j][2] * s1, acc[j][3] * s1);
    }
}

// ---------------------------------------------------------------------------
// Layer-0 GEMM (fp32 A, full 3-term split; off critical path): h16 = x @ W0
// ---------------------------------------------------------------------------
__global__ __launch_bounds__(512, 1)
void gemm_f32(const float* __restrict__ A, __half* __restrict__ C16) {
    extern __shared__ char sm[];
    const int tid  = threadIdx.x;
    const int wid  = tid >> 5;
    const int lane = tid & 31;
    const int bm   = blockIdx.x * MTILE;
    const uint32_t uBase = smem_u32(sm);

    fill_w_tiles<true>(sm, 2 * TILEB, 0, tid);

#pragma unroll
    for (int idx = tid; idx < MTILE * 32; idx += 512) {
        int r  = idx >> 5;
        int c4 = idx & 31;
        int row = bm + r;
        float4 v = make_float4(0.f, 0.f, 0.f, 0.f);
        if (row < NNODES)
            v = *(const float4*)&A[(size_t)row * 128 + c4 * 4];
        __half h0 = __float2half_rn(v.x), h1 = __float2half_rn(v.y);
        __half h2 = __float2half_rn(v.z), h3 = __float2half_rn(v.w);
        __half l0 = __float2half_rn(v.x - __half2float(h0));
        __half l1 = __float2half_rn(v.y - __half2float(h1));
        __half l2 = __float2half_rn(v.z - __half2float(h2));
        __half l3 = __float2half_rn(v.w - __half2float(h3));
        uint32_t off = (uint32_t)r * (PADH * 2) + c4 * 8;
        *(__half2*)(sm + off)             = __halves2half2(h0, h1);
        *(__half2*)(sm + off + 4)         = __halves2half2(h2, h3);
        *(__half2*)(sm + TILEB + off)     = __halves2half2(l0, l1);
        *(__half2*)(sm + TILEB + off + 4) = __halves2half2(l2, l3);
    }
    __syncthreads();

    mma_and_store<true, true, false>(uBase, uBase + 2 * TILEB, wid, lane, bm,
                                     nullptr, C16);
}

// ---------------------------------------------------------------------------
// Layers 1..2 GEMM (fp16 A exact, W_hi only — critical path):
//   out = fp16( dinv*(A@Whi) )
// ---------------------------------------------------------------------------
__global__ __launch_bounds__(512, 2)
void gemm_f16(const __half* __restrict__ A16, int wl,
              const float* __restrict__ dinv, __half* __restrict__ C16) {
    extern __shared__ char sm[];
    const int tid  = threadIdx.x;
    const int wid  = tid >> 5;
    const int lane = tid & 31;
    const int bm   = blockIdx.x * MTILE;
    const uint32_t uBase = smem_u32(sm);

    fill_w_tiles<false>(sm, TILEB, wl, tid);

    const uint2* ap = (const uint2*)A16;
#pragma unroll
    for (int idx = tid; idx < MTILE * 32; idx += 512) {
        int r  = idx >> 5;
        int c4 = idx & 31;
        int row = bm + r;
        uint2 u = make_uint2(0u, 0u);
        if (row < NNODES) u = __ldg(&ap[(size_t)row * 32 + c4]);
        uint32_t off = (uint32_t)r * (PADH * 2) + c4 * 8;
        *(uint2*)(sm + off) = u;
    }
    __syncthreads();

    mma_and_store<false, false, true>(uBase, uBase + TILEB, wid, lane, bm,
                                      dinv, C16);
}

// ---------------------------------------------------------------------------
// Gather: one warp per node (R9-optimal body: 8-deep unroll + scalar tail).
// SRC_SCALED: h already carries dinv[src]. FINAL_F32: write fp32.
// ---------------------------------------------------------------------------
#define ACCW(u, wgt) { \
    float2 _a = __half22float2(*(const __half2*)&(u).x); \
    float2 _b = __half22float2(*(const __half2*)&(u).y); \
    acc.x += _a.x * (wgt); acc.y += _a.y * (wgt); \
    acc.z += _b.x * (wgt); acc.w += _b.y * (wgt); }

template <bool SRC_SCALED, bool FINAL_F32>
__global__ __launch_bounds__(256)
void gather_k(const __half* __restrict__ hs, const float* __restrict__ bias,
              void* __restrict__ outv) {
    int w = (int)((blockIdx.x * (unsigned)blockDim.x + threadIdx.x) >> 5);
    if (w >= NNODES) return;
    int lane = threadIdx.x & 31;
    const uint2* hp = (const uint2*)hs;

    int e    = g_off[w];
    int eend = g_off[w + 1];
    float sc = __ldg(&g_dinv[w]);

    float4 acc = make_float4(0.f, 0.f, 0.f, 0.f);
    {
        uint2 u = __ldg(&hp[w * 32 + lane]);
        float wgt = SRC_SCALED ? 1.f : sc;
        ACCW(u, wgt)
    }

    for (; e + 8 <= eend; e += 8) {
        int s0 = __ldg(&g_csr[e + 0]);
        int s1 = __ldg(&g_csr[e + 1]);
        int s2 = __ldg(&g_csr[e + 2]);
        int s3 = __ldg(&g_csr[e + 3]);
        int s4 = __ldg(&g_csr[e + 4]);
        int s5 = __ldg(&g_csr[e + 5]);
        int s6 = __ldg(&g_csr[e + 6]);
        int s7 = __ldg(&g_csr[e + 7]);
        uint2 u0 = __ldg(&hp[s0 * 32 + lane]);
        uint2 u1 = __ldg(&hp[s1 * 32 + lane]);
        uint2 u2 = __ldg(&hp[s2 * 32 + lane]);
        uint2 u3 = __ldg(&hp[s3 * 32 + lane]);
        uint2 u4 = __ldg(&hp[s4 * 32 + lane]);
        uint2 u5 = __ldg(&hp[s5 * 32 + lane]);
        uint2 u6 = __ldg(&hp[s6 * 32 + lane]);
        uint2 u7 = __ldg(&hp[s7 * 32 + lane]);
        if (SRC_SCALED) {
            ACCW(u0, 1.f) ACCW(u1, 1.f) ACCW(u2, 1.f) ACCW(u3, 1.f)
            ACCW(u4, 1.f) ACCW(u5, 1.f) ACCW(u6, 1.f) ACCW(u7, 1.f)
        } else {
            ACCW(u0, __ldg(&g_dinv[s0])) ACCW(u1, __ldg(&g_dinv[s1]))
            ACCW(u2, __ldg(&g_dinv[s2])) ACCW(u3, __ldg(&g_dinv[s3]))
            ACCW(u4, __ldg(&g_dinv[s4])) ACCW(u5, __ldg(&g_dinv[s5]))
            ACCW(u6, __ldg(&g_dinv[s6])) ACCW(u7, __ldg(&g_dinv[s7]))
        }
    }
    for (; e < eend; e++) {
        int s = __ldg(&g_csr[e]);
        uint2 u = __ldg(&hp[s * 32 + lane]);
        float wgt = SRC_SCALED ? 1.f : __ldg(&g_dinv[s]);
        ACCW(u, wgt)
    }

    float4 bb = *(const float4*)&bias[lane * 4];
    acc.x = fmaxf(acc.x * sc + bb.x, 0.f);
    acc.y = fmaxf(acc.y * sc + bb.y, 0.f);
    acc.z = fmaxf(acc.z * sc + bb.z, 0.f);
    acc.w = fmaxf(acc.w * sc + bb.w, 0.f);

    if (FINAL_F32) {
        ((float4*)outv)[w * 32 + lane] = acc;
    } else {
        __half2 o0 = __floats2half2_rn(acc.x, acc.y);
        __half2 o1 = __floats2half2_rn(acc.z, acc.w);
        uint2 ou;
        ou.x = *(const uint32_t*)&o0;
        ou.y = *(const uint32_t*)&o1;
        ((uint2*)outv)[w * 32 + lane] = ou;
    }
}
#undef ACCW

// ---------------------------------------------------------------------------
extern "C" void kernel_launch(void* const* d_in, const int* in_sizes, int n_in,
                              void* d_out, int out_size) {
    const float* x  = (const float*)d_in[0];
    const int*   ei = (const int*)d_in[1];
    const float* W0 = (const float*)d_in[2];
    const float* b0 = (const float*)d_in[3];
    const float* W1 = (const float*)d_in[4];
    const float* b1 = (const float*)d_in[5];
    const float* W2 = (const float*)d_in[6];
    const float* b2 = (const float*)d_in[7];
    const int* src = ei;
    const int* dst = ei + EEDGES;

    __half *ha, *hb;
    float* dinv;
    cudaGetSymbolAddress((void**)&ha, g_h16a);
    cudaGetSymbolAddress((void**)&hb, g_h16b);
    cudaGetSymbolAddress((void**)&dinv, g_dinv);

    cudaFuncSetAttribute(gemm_f32, cudaFuncAttributeMaxDynamicSharedMemorySize, SMEM_L0);
    cudaFuncSetAttribute(gemm_f16, cudaFuncAttributeMaxDynamicSharedMemorySize, SMEM_F16);

    static cudaStream_t s2 = nullptr;
    static cudaEvent_t evFork = nullptr, evJoin = nullptr;
    if (!s2) {
        cudaStreamCreateWithFlags(&s2, cudaStreamNonBlocking);
        cudaEventCreateWithFlags(&evFork, cudaEventDisableTiming);
        cudaEventCreateWithFlags(&evJoin, cudaEventDisableTiming);
    }

    // Fork: side stream does W prep + layer-0 GEMM (independent of CSR chain)
    cudaEventRecord(evFork, 0);
    cudaStreamWaitEvent(s2, evFork, 0);
    prep_w<<<(3 * 16384 + 255) / 256, 256, 0, s2>>>(W0, W1, W2);
    gemm_f32<<<NTILES, 512, SMEM_L0, s2>>>(x, ha);
    cudaEventRecord(evJoin, s2);

    // Main stream: degree + CSR build (g_deg is zero on entry by invariant)
    deg_count<<<(EEDGES / 4 + 255) / 256, 256>>>(dst);
    scan1<<<NSCAN, SCAN_T>>>();
    scan2p<<<1, 128>>>();
    scan3<<<(NNODES + 255) / 256, 256>>>();
    csr_fill<<<(EEDGES / 4 + 255) / 256, 256>>>(src, dst);

    // Join, then the serial layer chain
    cudaStreamWaitEvent(0, evJoin, 0);

    const int gather_blocks = (NNODES + 7) / 8;
    gather_k<false, false><<<gather_blocks, 256>>>(ha, b0, hb);
    gemm_f16<<<NTILES, 512, SMEM_F16>>>(hb, 1, dinv, ha);
    gather_k<true, false><<<gather_blocks, 256>>>(ha, b1, hb);
    gemm_f16<<<NTILES, 512, SMEM_F16>>>(hb, 2, dinv, ha);
    gather_k<true, true><<<gather_blocks, 256>>>(ha, b2, d_out);
}

// round 17
// speedup vs baseline: 1.2739x; 1.0376x over previous
#include <cuda_runtime.h>
#include <cuda_fp16.h>
#include <cstdint>

#define NNODES 100000
#define EEDGES 1600000
#define HDIM   128

#define SCAN_BLK 1024
#define SCAN_T   256
#define NSCAN    ((NNODES + SCAN_BLK - 1) / SCAN_BLK)   // 98

#define MTILE   128
#define NTILES  ((NNODES + MTILE - 1) / MTILE)          // 782
#define PADH    136                                      // halves per padded row (272 B)
#define TILEB   (128 * PADH * 2)                         // 34816 B per fp16 tile
#define SMEM_L0 (3 * TILEB)                              // A, W_hi, W_lo
#define SMEM_F16 (2 * TILEB)                             // A, W_hi

// ---------------------------------------------------------------------------
// Scratch (device globals). g_deg invariant: zero at kernel_launch entry
// (BSS-zero initially; scan3 re-zeroes it each run for the next replay).
// ---------------------------------------------------------------------------
__device__ __half g_h16a[(size_t)NNODES * HDIM];  // ping
__device__ __half g_h16b[(size_t)NNODES * HDIM];  // pong
__device__ float  g_dinv[NNODES];
__device__ int    g_deg[NNODES];
__device__ int    g_off[NNODES + 1];
__device__ int    g_cur[NNODES];
__device__ int    g_csr[EEDGES];
__device__ int    g_bsum[NSCAN];
__device__ int    g_bbase[NSCAN];
__device__ __half g_Wt[3][2][128 * 128];          // k-major W, fp16 hi/lo split

// ---------------------------------------------------------------------------
__device__ __forceinline__ uint32_t smem_u32(const void* p) {
    uint32_t a;
    asm("{ .reg .u64 t; cvta.to.shared.u64 t, %1; cvt.u32.u64 %0, t; }"
        : "=r"(a) : "l"(p));
    return a;
}

#define LDSM_X4(r, a) \
    asm volatile("ldmatrix.sync.aligned.m8n8.x4.shared.b16 {%0,%1,%2,%3}, [%4];" \
                 : "=r"((r)[0]), "=r"((r)[1]), "=r"((r)[2]), "=r"((r)[3]) : "r"(a))
#define LDSM_X4T(r, a) \
    asm volatile("ldmatrix.sync.aligned.m8n8.x4.trans.shared.b16 {%0,%1,%2,%3}, [%4];" \
                 : "=r"((r)[0]), "=r"((r)[1]), "=r"((r)[2]), "=r"((r)[3]) : "r"(a))
#define MMA_F16(c, a, b0, b1) \
    asm volatile("mma.sync.aligned.m16n8k16.row.col.f32.f16.f16.f32 " \
                 "{%0,%1,%2,%3}, {%4,%5,%6,%7}, {%8,%9}, {%0,%1,%2,%3};" \
                 : "+f"((c)[0]), "+f"((c)[1]), "+f"((c)[2]), "+f"((c)[3]) \
                 : "r"((a)[0]), "r"((a)[1]), "r"((a)[2]), "r"((a)[3]), \
                   "r"(b0), "r"(b1))

// ---------------------------------------------------------------------------
// Degree / CSR build
// ---------------------------------------------------------------------------
__global__ void deg_count(const int* __restrict__ dst) {
    int t = blockIdx.x * blockDim.x + threadIdx.x;   // over EEDGES/4
    if (t < EEDGES / 4) {
        int4 d = ((const int4*)dst)[t];
        atomicAdd(&g_deg[d.x], 1);
        atomicAdd(&g_deg[d.y], 1);
        atomicAdd(&g_deg[d.z], 1);
        atomicAdd(&g_deg[d.w], 1);
    }
}
// scan1 also computes dinv = rsqrt(deg+1)
__global__ __launch_bounds__(SCAN_T)
void scan1() {
    __shared__ int sh[SCAN_T];
    int b = blockIdx.x, t = threadIdx.x;
    int base = b * SCAN_BLK + t * 4;
    int v[4];
#pragma unroll
    for (int j = 0; j < 4; j++) {
        int i = base + j;
        v[j] = (i < NNODES) ? g_deg[i] : 0;
        if (i < NNODES) g_dinv[i] = rsqrtf((float)v[j] + 1.0f);
    }
    int tot = v[0] + v[1] + v[2] + v[3];
    sh[t] = tot;
    __syncthreads();
    for (int o = 1; o < SCAN_T; o <<= 1) {
        int x = 0;
        if (t >= o) x = sh[t - o];
        __syncthreads();
        sh[t] += x;
        __syncthreads();
    }
    int run = sh[t] - tot;
#pragma unroll
    for (int j = 0; j < 4; j++) {
        int i = base + j;
        if (i < NNODES) g_off[i] = run;
        run += v[j];
    }
    if (t == SCAN_T - 1) g_bsum[b] = sh[t];
}
__global__ void scan2p() {
    __shared__ int sh[128];
    int t = threadIdx.x;
    int v = (t < NSCAN) ? g_bsum[t] : 0;
    sh[t] = v;
    __syncthreads();
    for (int o = 1; o < 128; o <<= 1) {
        int x = 0;
        if (t >= o) x = sh[t - o];
        __syncthreads();
        sh[t] += x;
        __syncthreads();
    }
    if (t < NSCAN) g_bbase[t] = sh[t] - v;
    if (t == 127) g_off[NNODES] = sh[127];
}
// scan3 also re-zeroes g_deg (restores the zero-on-entry invariant).
__global__ void scan3() {
    int i = blockIdx.x * blockDim.x + threadIdx.x;
    if (i < NNODES) {
        int v = g_off[i] + g_bbase[i / SCAN_BLK];
        g_off[i] = v;
        g_cur[i] = v;
        g_deg[i] = 0;
    }
}
__global__ void csr_fill(const int* __restrict__ src, const int* __restrict__ dst) {
    int t = blockIdx.x * blockDim.x + threadIdx.x;   // over EEDGES/4
    if (t < EEDGES / 4) {
        int4 d = ((const int4*)dst)[t];
        int4 s = ((const int4*)src)[t];
        g_csr[atomicAdd(&g_cur[d.x], 1)] = s.x;
        g_csr[atomicAdd(&g_cur[d.y], 1)] = s.y;
        g_csr[atomicAdd(&g_cur[d.z], 1)] = s.z;
        g_csr[atomicAdd(&g_cur[d.w], 1)] = s.w;
    }
}

// ---------------------------------------------------------------------------
// Prep: split W (k-major, [k][n]) into fp16 hi/lo (near-exact sum).
// ---------------------------------------------------------------------------
__global__ void prep_w(const float* __restrict__ W0, const float* __restrict__ W1,
                       const float* __restrict__ W2) {
    int idx = blockIdx.x * blockDim.x + threadIdx.x;
    if (idx >= 3 * 16384) return;
    int l = idx >> 14;
    int e = idx & 16383;
    const float* W = (l == 0) ? W0 : (l == 1) ? W1 : W2;
    float v = W[e];
    __half hi = __float2half_rn(v);
    __half lo = __float2half_rn(v - __half2float(hi));
    g_Wt[l][0][e] = hi;
    g_Wt[l][1][e] = lo;
}

// ---------------------------------------------------------------------------
// GEMM device helpers
// ---------------------------------------------------------------------------
template <bool LO>
__device__ __forceinline__ void fill_w_tiles(char* sm, uint32_t woff, int wl,
                                             int tid) {
    const uint4* whi = (const uint4*)g_Wt[wl][0];
    const uint4* wlo = (const uint4*)g_Wt[wl][1];
#pragma unroll
    for (int i = tid; i < 2048; i += 512) {
        int r  = i >> 4;
        int c4 = i & 15;
        uint32_t off = (uint32_t)r * (PADH * 2) + c4 * 16;
        *(uint4*)(sm + woff + off) = __ldg(&whi[i]);
        if (LO) *(uint4*)(sm + woff + TILEB + off) = __ldg(&wlo[i]);
    }
}

// MMA core. DUAL_B: W_lo tile at uWhi+TILEB adds Ahi*Wlo. SCALE: dinv epilogue.
template <bool DUAL_B, bool SCALE>
__device__ __forceinline__ void mma_and_store(uint32_t uA, uint32_t uWhi,
                                              int wid, int lane, int bm,
                                              const float* dinv,
                                              __half* __restrict__ C16) {
    const uint32_t uWlo = uWhi + TILEB;
    const int mt = wid >> 1;
    const int nh = wid & 1;
    const int lr = lane & 15;
    const int lc = lane >> 4;

    float acc[8][4];
#pragma unroll
    for (int j = 0; j < 8; j++)
#pragma unroll
        for (int q = 0; q < 4; q++) acc[j][q] = 0.0f;

#pragma unroll
    for (int ks = 0; ks < 8; ks++) {
        uint32_t aoff = (uint32_t)(mt * 16 + lr) * (PADH * 2) + (ks * 16 + lc * 8) * 2;
        uint32_t aH[4];
        LDSM_X4(aH, uA + aoff);

        uint32_t brow = (uint32_t)(ks * 16 + lr) * (PADH * 2);
#pragma unroll
        for (int p = 0; p < 4; p++) {
            uint32_t boff = brow + (nh * 64 + p * 16 + lc * 8) * 2;
            uint32_t bH[4];
            LDSM_X4T(bH, uWhi + boff);
            MMA_F16(acc[2 * p],     aH, bH[0], bH[1]);
            MMA_F16(acc[2 * p + 1], aH, bH[2], bH[3]);
            if (DUAL_B) {
                uint32_t bL[4];
                LDSM_X4T(bL, uWlo + boff);
                MMA_F16(acc[2 * p],     aH, bL[0], bL[1]);
                MMA_F16(acc[2 * p + 1], aH, bL[2], bL[3]);
            }
        }
    }

    int row0 = bm + mt * 16 + (lane >> 2);
    int row1 = row0 + 8;
    float s0 = 1.f, s1 = 1.f;
    if (SCALE) {
        s0 = (row0 < NNODES) ? __ldg(&dinv[row0]) : 0.f;
        s1 = (row1 < NNODES) ? __ldg(&dinv[row1]) : 0.f;
    }
    int colb = nh * 64 + (lane & 3) * 2;
    if (row0 < NNODES) {
        __half* o = &C16[(size_t)row0 * 128 + colb];
#pragma unroll
        for (int j = 0; j < 8; j++)
            *(__half2*)(o + j * 8) = __floats2half2_rn(acc[j][0] * s0, acc[j][1] * s0);
    }
    if (row1 < NNODES) {
        __half* o = &C16[(size_t)row1 * 128 + colb];
#pragma unroll
        for (int j = 0; j < 8; j++)
            *(__half2*)(o + j * 8) = __floats2half2_rn(acc[j][2] * s1, acc[j][3] * s1);
    }
}

// ---------------------------------------------------------------------------
// Layer-0 GEMM (fp32 A rounded to fp16; W hi+lo both terms):
//   h16 = fp16( fp16(x) @ (Whi + Wlo) ),  2 CTAs/SM.
// ---------------------------------------------------------------------------
__global__ __launch_bounds__(512, 2)
void gemm_f32(const float* __restrict__ A, __half* __restrict__ C16) {
    extern __shared__ char sm[];
    const int tid  = threadIdx.x;
    const int wid  = tid >> 5;
    const int lane = tid & 31;
    const int bm   = blockIdx.x * MTILE;
    const uint32_t uBase = smem_u32(sm);

    fill_w_tiles<true>(sm, TILEB, 0, tid);

#pragma unroll
    for (int idx = tid; idx < MTILE * 32; idx += 512) {
        int r  = idx >> 5;
        int c4 = idx & 31;
        int row = bm + r;
        float4 v = make_float4(0.f, 0.f, 0.f, 0.f);
        if (row < NNODES)
            v = *(const float4*)&A[(size_t)row * 128 + c4 * 4];
        uint32_t off = (uint32_t)r * (PADH * 2) + c4 * 8;
        *(__half2*)(sm + off)     = __floats2half2_rn(v.x, v.y);
        *(__half2*)(sm + off + 4) = __floats2half2_rn(v.z, v.w);
    }
    __syncthreads();

    mma_and_store<true, false>(uBase, uBase + TILEB, wid, lane, bm, nullptr, C16);
}

// ---------------------------------------------------------------------------
// Layers 1..2 GEMM (fp16 A exact, W_hi only): out = fp16( dinv*(A@Whi) )
// ---------------------------------------------------------------------------
__global__ __launch_bounds__(512, 2)
void gemm_f16(const __half* __restrict__ A16, int wl,
              const float* __restrict__ dinv, __half* __restrict__ C16) {
    extern __shared__ char sm[];
    const int tid  = threadIdx.x;
    const int wid  = tid >> 5;
    const int lane = tid & 31;
    const int bm   = blockIdx.x * MTILE;
    const uint32_t uBase = smem_u32(sm);

    fill_w_tiles<false>(sm, TILEB, wl, tid);

    const uint2* ap = (const uint2*)A16;
#pragma unroll
    for (int idx = tid; idx < MTILE * 32; idx += 512) {
        int r  = idx >> 5;
        int c4 = idx & 31;
        int row = bm + r;
        uint2 u = make_uint2(0u, 0u);
        if (row < NNODES) u = __ldg(&ap[(size_t)row * 32 + c4]);
        uint32_t off = (uint32_t)r * (PADH * 2) + c4 * 8;
        *(uint2*)(sm + off) = u;
    }
    __syncthreads();

    mma_and_store<false, true>(uBase, uBase + TILEB, wid, lane, bm, dinv, C16);
}

// ---------------------------------------------------------------------------
// Gather: one warp per node (R9-optimal body: 8-deep unroll + scalar tail).
// SRC_SCALED: h already carries dinv[src]. FINAL_F32: write fp32.
// ---------------------------------------------------------------------------
#define ACCW(u, wgt) { \
    float2 _a = __half22float2(*(const __half2*)&(u).x); \
    float2 _b = __half22float2(*(const __half2*)&(u).y); \
    acc.x += _a.x * (wgt); acc.y += _a.y * (wgt); \
    acc.z += _b.x * (wgt); acc.w += _b.y * (wgt); }

template <bool SRC_SCALED, bool FINAL_F32>
__global__ __launch_bounds__(256)
void gather_k(const __half* __restrict__ hs, const float* __restrict__ bias,
              void* __restrict__ outv) {
    int w = (int)((blockIdx.x * (unsigned)blockDim.x + threadIdx.x) >> 5);
    if (w >= NNODES) return;
    int lane = threadIdx.x & 31;
    const uint2* hp = (const uint2*)hs;

    int e    = g_off[w];
    int eend = g_off[w + 1];
    float sc = __ldg(&g_dinv[w]);

    float4 acc = make_float4(0.f, 0.f, 0.f, 0.f);
    {
        uint2 u = __ldg(&hp[w * 32 + lane]);
        float wgt = SRC_SCALED ? 1.f : sc;
        ACCW(u, wgt)
    }

    for (; e + 8 <= eend; e += 8) {
        int s0 = __ldg(&g_csr[e + 0]);
        int s1 = __ldg(&g_csr[e + 1]);
        int s2 = __ldg(&g_csr[e + 2]);
        int s3 = __ldg(&g_csr[e + 3]);
        int s4 = __ldg(&g_csr[e + 4]);
        int s5 = __ldg(&g_csr[e + 5]);
        int s6 = __ldg(&g_csr[e + 6]);
        int s7 = __ldg(&g_csr[e + 7]);
        uint2 u0 = __ldg(&hp[s0 * 32 + lane]);
        uint2 u1 = __ldg(&hp[s1 * 32 + lane]);
        uint2 u2 = __ldg(&hp[s2 * 32 + lane]);
        uint2 u3 = __ldg(&hp[s3 * 32 + lane]);
        uint2 u4 = __ldg(&hp[s4 * 32 + lane]);
        uint2 u5 = __ldg(&hp[s5 * 32 + lane]);
        uint2 u6 = __ldg(&hp[s6 * 32 + lane]);
        uint2 u7 = __ldg(&hp[s7 * 32 + lane]);
        if (SRC_SCALED) {
            ACCW(u0, 1.f) ACCW(u1, 1.f) ACCW(u2, 1.f) ACCW(u3, 1.f)
            ACCW(u4, 1.f) ACCW(u5, 1.f) ACCW(u6, 1.f) ACCW(u7, 1.f)
        } else {
            ACCW(u0, __ldg(&g_dinv[s0])) ACCW(u1, __ldg(&g_dinv[s1]))
            ACCW(u2, __ldg(&g_dinv[s2])) ACCW(u3, __ldg(&g_dinv[s3]))
            ACCW(u4, __ldg(&g_dinv[s4])) ACCW(u5, __ldg(&g_dinv[s5]))
            ACCW(u6, __ldg(&g_dinv[s6])) ACCW(u7, __ldg(&g_dinv[s7]))
        }
    }
    for (; e < eend; e++) {
        int s = __ldg(&g_csr[e]);
        uint2 u = __ldg(&hp[s * 32 + lane]);
        float wgt = SRC_SCALED ? 1.f : __ldg(&g_dinv[s]);
        ACCW(u, wgt)
    }

    float4 bb = *(const float4*)&bias[lane * 4];
    acc.x = fmaxf(acc.x * sc + bb.x, 0.f);
    acc.y = fmaxf(acc.y * sc + bb.y, 0.f);
    acc.z = fmaxf(acc.z * sc + bb.z, 0.f);
    acc.w = fmaxf(acc.w * sc + bb.w, 0.f);

    if (FINAL_F32) {
        ((float4*)outv)[w * 32 + lane] = acc;
    } else {
        __half2 o0 = __floats2half2_rn(acc.x, acc.y);
        __half2 o1 = __floats2half2_rn(acc.z, acc.w);
        uint2 ou;
        ou.x = *(const uint32_t*)&o0;
        ou.y = *(const uint32_t*)&o1;
        ((uint2*)outv)[w * 32 + lane] = ou;
    }
}
#undef ACCW

// ---------------------------------------------------------------------------
extern "C" void kernel_launch(void* const* d_in, const int* in_sizes, int n_in,
                              void* d_out, int out_size) {
    const float* x  = (const float*)d_in[0];
    const int*   ei = (const int*)d_in[1];
    const float* W0 = (const float*)d_in[2];
    const float* b0 = (const float*)d_in[3];
    const float* W1 = (const float*)d_in[4];
    const float* b1 = (const float*)d_in[5];
    const float* W2 = (const float*)d_in[6];
    const float* b2 = (const float*)d_in[7];
    const int* src = ei;
    const int* dst = ei + EEDGES;

    __half *ha, *hb;
    float* dinv;
    cudaGetSymbolAddress((void**)&ha, g_h16a);
    cudaGetSymbolAddress((void**)&hb, g_h16b);
    cudaGetSymbolAddress((void**)&dinv, g_dinv);

    cudaFuncSetAttribute(gemm_f32, cudaFuncAttributeMaxDynamicSharedMemorySize, SMEM_L0);
    cudaFuncSetAttribute(gemm_f16, cudaFuncAttributeMaxDynamicSharedMemorySize, SMEM_F16);

    static cudaStream_t s2 = nullptr;
    static cudaEvent_t evFork = nullptr, evJoin = nullptr;
    if (!s2) {
        cudaStreamCreateWithFlags(&s2, cudaStreamNonBlocking);
        cudaEventCreateWithFlags(&evFork, cudaEventDisableTiming);
        cudaEventCreateWithFlags(&evJoin, cudaEventDisableTiming);
    }

    // Fork: side stream does W prep + layer-0 GEMM
    cudaEventRecord(evFork, 0);
    cudaStreamWaitEvent(s2, evFork, 0);
    prep_w<<<(3 * 16384 + 255) / 256, 256, 0, s2>>>(W0, W1, W2);
    gemm_f32<<<NTILES, 512, SMEM_L0, s2>>>(x, ha);
    cudaEventRecord(evJoin, s2);

    // Main stream: degree + CSR build (g_deg is zero on entry by invariant)
    deg_count<<<(EEDGES / 4 + 255) / 256, 256>>>(dst);
    scan1<<<NSCAN, SCAN_T>>>();
    scan2p<<<1, 128>>>();
    scan3<<<(NNODES + 255) / 256, 256>>>();
    csr_fill<<<(EEDGES / 4 + 255) / 256, 256>>>(src, dst);

    // Join, then the serial layer chain
    cudaStreamWaitEvent(0, evJoin, 0);

    const int gather_blocks = (NNODES + 7) / 8;
    gather_k<false, false><<<gather_blocks, 256>>>(ha, b0, hb);
    gemm_f16<<<NTILES, 512, SMEM_F16>>>(hb, 1, dinv, ha);
    gather_k<true, false><<<gather_blocks, 256>>>(ha, b1, hb);
    gemm_f16<<<NTILES, 512, SMEM_F16>>>(hb, 2, dinv, ha);
    gather_k<true, true><<<gather_blocks, 256>>>(ha, b2, d_out);
}